// round 1
// baseline (speedup 1.0000x reference)
#include <cuda_runtime.h>
#include <math.h>

#define BB 2
#define SS 4096
#define EE 1024
#define HH 16
#define DD 64
#define WW 256

// Scratch (allocation-free: __device__ globals)
// Q, K stored transposed [B,H,D,S] for coalesced attention loads; V as [B,H,S,D].
__device__ __align__(16) float g_QT[BB * HH * DD * SS];
__device__ __align__(16) float g_KT[BB * HH * DD * SS];
__device__ __align__(16) float g_V [BB * HH * SS * DD];

// ---------------------------------------------------------------------------
// QKV projection GEMM: C[m,n] = sum_k X[m,k] * W[n,k] + bias[n]
// M = B*S = 8192, N = E = 1024, K = E = 1024.
// MODE 0: write Q transposed [B,H,D,S], scaled by 1/8
// MODE 1: write K transposed [B,H,D,S]
// MODE 2: write V [B,H,S,D]
// ---------------------------------------------------------------------------
template <int MODE>
__global__ void __launch_bounds__(256) qkv_gemm(const float* __restrict__ X,
                                               const float* __restrict__ Wm,
                                               const float* __restrict__ bias) {
    __shared__ float As[16][128];
    __shared__ float Bs[16][128];

    const int tid = threadIdx.x;
    const int m0 = blockIdx.y * 128;
    const int n0 = blockIdx.x * 128;
    const int tx = tid & 15;
    const int ty = tid >> 4;

    const int lr = tid >> 2;          // 0..63
    const int lc = (tid & 3) * 4;     // 0,4,8,12

    float acc[8][8];
#pragma unroll
    for (int i = 0; i < 8; i++)
#pragma unroll
        for (int j = 0; j < 8; j++) acc[i][j] = 0.f;

    for (int k0 = 0; k0 < EE; k0 += 16) {
        float4 a0 = *(const float4*)&X[(m0 + lr) * EE + k0 + lc];
        float4 a1 = *(const float4*)&X[(m0 + lr + 64) * EE + k0 + lc];
        float4 b0 = *(const float4*)&Wm[(n0 + lr) * EE + k0 + lc];
        float4 b1 = *(const float4*)&Wm[(n0 + lr + 64) * EE + k0 + lc];
        __syncthreads();
        As[lc + 0][lr] = a0.x; As[lc + 1][lr] = a0.y;
        As[lc + 2][lr] = a0.z; As[lc + 3][lr] = a0.w;
        As[lc + 0][lr + 64] = a1.x; As[lc + 1][lr + 64] = a1.y;
        As[lc + 2][lr + 64] = a1.z; As[lc + 3][lr + 64] = a1.w;
        Bs[lc + 0][lr] = b0.x; Bs[lc + 1][lr] = b0.y;
        Bs[lc + 2][lr] = b0.z; Bs[lc + 3][lr] = b0.w;
        Bs[lc + 0][lr + 64] = b1.x; Bs[lc + 1][lr + 64] = b1.y;
        Bs[lc + 2][lr + 64] = b1.z; Bs[lc + 3][lr + 64] = b1.w;
        __syncthreads();
#pragma unroll
        for (int kk = 0; kk < 16; ++kk) {
            float a[8], b[8];
            *(float4*)(a)     = *(float4*)&As[kk][ty * 8];
            *(float4*)(a + 4) = *(float4*)&As[kk][ty * 8 + 4];
            *(float4*)(b)     = *(float4*)&Bs[kk][tx * 8];
            *(float4*)(b + 4) = *(float4*)&Bs[kk][tx * 8 + 4];
#pragma unroll
            for (int i = 0; i < 8; i++)
#pragma unroll
                for (int j = 0; j < 8; j++) acc[i][j] += a[i] * b[j];
        }
    }

#pragma unroll
    for (int i = 0; i < 8; i++) {
        const int row = m0 + ty * 8 + i;
        const int bb = row / SS;
        const int s = row % SS;
#pragma unroll
        for (int j = 0; j < 8; j++) {
            const int n = n0 + tx * 8 + j;
            float v = acc[i][j] + bias[n];
            const int h = n >> 6;
            const int d = n & 63;
            if (MODE == 0) {
                g_QT[((bb * HH + h) * DD + d) * SS + s] = v * 0.125f;
            } else if (MODE == 1) {
                g_KT[((bb * HH + h) * DD + d) * SS + s] = v;
            } else {
                g_V[((bb * HH + h) * SS + s) * DD + d] = v;
            }
        }
    }
}

// ---------------------------------------------------------------------------
// Banded flash attention.
// One block = (b, h, 64-query tile). 256 threads = 16x16 (ty: 4-query group,
// tx: 4-key/4-headdim group). Online softmax across 9 key tiles of 64
// covering [q0-256, q0+320).
// ---------------------------------------------------------------------------
#define NQT (SS / 64)
#define PS_STRIDE 68
#define ATT_SMEM_FLOATS (4096 * 3 + 64 * PS_STRIDE + 64 + 64 + 64)
#define ATT_SMEM_BYTES (ATT_SMEM_FLOATS * 4)

__global__ void __launch_bounds__(256) banded_attn(const int* __restrict__ amask,
                                                   float* __restrict__ out) {
    extern __shared__ float sm[];
    float* Qs = sm;                 // [d][q]  64x64
    float* Ks = Qs + 4096;          // [d][k]  64x64
    float* Vs = Ks + 4096;          // [k][d]  64x64
    float* Ps = Vs + 4096;          // [k][q]  64x68 (padded)
    float* ms = Ps + 64 * PS_STRIDE;
    float* ls = ms + 64;
    float* fms = ls + 64;

    const int tid = threadIdx.x;
    const int qt = blockIdx.x % NQT;
    const int h = (blockIdx.x / NQT) % HH;
    const int b = blockIdx.x / (NQT * HH);
    const int q0 = qt * 64;
    const int bh = b * HH + h;
    const int tx = tid & 15;
    const int ty = tid >> 4;

    // Load Q tile (transposed layout in gmem -> direct coalesced copy)
    {
        const int c4 = tx * 4;
#pragma unroll
        for (int r = 0; r < 4; r++) {
            const int d = ty + r * 16;
            float4 v = *(const float4*)&g_QT[(bh * DD + d) * SS + q0 + c4];
            *(float4*)&Qs[d * 64 + c4] = v;
        }
    }
    if (tid < 64) { ms[tid] = -1e30f; ls[tid] = 0.f; }

    float o[4][4];
#pragma unroll
    for (int i = 0; i < 4; i++)
#pragma unroll
        for (int j = 0; j < 4; j++) o[i][j] = 0.f;

    for (int kt = 0; kt < 9; ++kt) {
        const int j0 = q0 - WW + kt * 64;
        if (j0 + 64 <= 0 || j0 >= SS) continue;  // uniform skip
        __syncthreads();

        // Load K (transposed), V, and additive mask for this key tile
        {
            const int c4 = tx * 4;
#pragma unroll
            for (int r = 0; r < 4; r++) {
                const int d = ty + r * 16;
                float kv0, kv1, kv2, kv3;
                int j = j0 + c4;
                kv0 = (j >= 0 && j < SS) ? g_KT[(bh * DD + d) * SS + j] : 0.f;
                kv1 = (j + 1 >= 0 && j + 1 < SS) ? g_KT[(bh * DD + d) * SS + j + 1] : 0.f;
                kv2 = (j + 2 >= 0 && j + 2 < SS) ? g_KT[(bh * DD + d) * SS + j + 2] : 0.f;
                kv3 = (j + 3 >= 0 && j + 3 < SS) ? g_KT[(bh * DD + d) * SS + j + 3] : 0.f;
                *(float4*)&Ks[d * 64 + c4] = make_float4(kv0, kv1, kv2, kv3);

                const int k = ty + r * 16;
                const int jv = j0 + k;
                float4 vv;
                if (jv >= 0 && jv < SS)
                    vv = *(const float4*)&g_V[(bh * SS + jv) * DD + c4];
                else
                    vv = make_float4(0.f, 0.f, 0.f, 0.f);
                *(float4*)&Vs[k * 64 + c4] = vv;
            }
            if (tid < 64) {
                const int j = j0 + tid;
                fms[tid] = (j >= 0 && j < SS && amask[b * SS + j] != 0) ? -10000.f : 0.f;
            }
        }
        __syncthreads();

        // Scores: S[q][k] = Q . K, 4x4 microtile per thread
        float sacc[4][4];
#pragma unroll
        for (int i = 0; i < 4; i++)
#pragma unroll
            for (int j = 0; j < 4; j++) sacc[i][j] = 0.f;

#pragma unroll 8
        for (int d = 0; d < 64; ++d) {
            float4 q4 = *(float4*)&Qs[d * 64 + ty * 4];
            float4 k4 = *(float4*)&Ks[d * 64 + tx * 4];
            const float* qa = (const float*)&q4;
            const float* ka = (const float*)&k4;
#pragma unroll
            for (int i = 0; i < 4; i++)
#pragma unroll
                for (int j = 0; j < 4; j++) sacc[i][j] += qa[i] * ka[j];
        }

        // Mask + online softmax update
        float mloc[4], fscale[4], rsum[4];
#pragma unroll
        for (int ii = 0; ii < 4; ++ii) {
            const int i = q0 + ty * 4 + ii;
            float svr[4];
            float rm = -INFINITY;
#pragma unroll
            for (int jj = 0; jj < 4; jj++) {
                const int j = j0 + tx * 4 + jj;
                const bool valid = (j >= 0) && (j < SS) && (j - i <= WW) && (i - j <= WW);
                const float sv = valid ? sacc[ii][jj] + fms[tx * 4 + jj] : -INFINITY;
                svr[jj] = sv;
                rm = fmaxf(rm, sv);
            }
#pragma unroll
            for (int off = 1; off < 16; off <<= 1)
                rm = fmaxf(rm, __shfl_xor_sync(0xffffffffu, rm, off));
            const float mo = ms[ty * 4 + ii];
            const float mn = fmaxf(mo, rm);   // >= -1e30, never -inf
            mloc[ii] = mn;
            fscale[ii] = __expf(mo - mn);
            float rs = 0.f;
#pragma unroll
            for (int jj = 0; jj < 4; jj++) {
                const float pv = __expf(svr[jj] - mn);
                rs += pv;
                Ps[(tx * 4 + jj) * PS_STRIDE + ty * 4 + ii] = pv;
            }
#pragma unroll
            for (int off = 1; off < 16; off <<= 1)
                rs += __shfl_xor_sync(0xffffffffu, rs, off);
            rsum[ii] = rs;
#pragma unroll
            for (int jj = 0; jj < 4; jj++) o[ii][jj] *= fscale[ii];
        }
        __syncthreads();
        if (tx == 0) {
#pragma unroll
            for (int ii = 0; ii < 4; ii++) {
                const int ql = ty * 4 + ii;
                ms[ql] = mloc[ii];
                ls[ql] = ls[ql] * fscale[ii] + rsum[ii];
            }
        }

        // O += P . V
#pragma unroll 8
        for (int k = 0; k < 64; ++k) {
            float4 p4 = *(float4*)&Ps[k * PS_STRIDE + ty * 4];
            float4 v4 = *(float4*)&Vs[k * 64 + tx * 4];
            const float* pa = (const float*)&p4;
            const float* va = (const float*)&v4;
#pragma unroll
            for (int i = 0; i < 4; i++)
#pragma unroll
                for (int j = 0; j < 4; j++) o[i][j] += pa[i] * va[j];
        }
    }

    __syncthreads();
#pragma unroll
    for (int ii = 0; ii < 4; ii++) {
        const float inv = 1.f / ls[ty * 4 + ii];
        const int i = q0 + ty * 4 + ii;
        float4 ov = make_float4(o[ii][0] * inv, o[ii][1] * inv,
                                o[ii][2] * inv, o[ii][3] * inv);
        *(float4*)&out[(b * SS + i) * EE + h * 64 + tx * 4] = ov;
    }
}

// ---------------------------------------------------------------------------
extern "C" void kernel_launch(void* const* d_in, const int* in_sizes, int n_in,
                              void* d_out, int out_size) {
    const float* hs   = (const float*)d_in[0];
    const int*   am   = (const int*)d_in[1];
    const float* q_w  = (const float*)d_in[2];
    const float* q_b  = (const float*)d_in[3];
    const float* k_w  = (const float*)d_in[4];
    const float* k_b  = (const float*)d_in[5];
    const float* v_w  = (const float*)d_in[6];
    const float* v_b  = (const float*)d_in[7];
    float* out = (float*)d_out;

    cudaFuncSetAttribute(banded_attn, cudaFuncAttributeMaxDynamicSharedMemorySize,
                         ATT_SMEM_BYTES);

    dim3 g(EE / 128, (BB * SS) / 128);  // (8, 64)
    qkv_gemm<0><<<g, 256>>>(hs, q_w, q_b);
    qkv_gemm<1><<<g, 256>>>(hs, k_w, k_b);
    qkv_gemm<2><<<g, 256>>>(hs, v_w, v_b);

    banded_attn<<<BB * HH * NQT, 256, ATT_SMEM_BYTES>>>(am, out);
}

// round 2
// speedup vs baseline: 1.0505x; 1.0505x over previous
#include <cuda_runtime.h>
#include <math.h>

#define BB 2
#define SS 4096
#define EE 1024
#define HH 16
#define DD 64
#define WW 256

typedef unsigned long long u64;

__device__ __forceinline__ u64 bcast2(float x) {
    u64 r; asm("mov.b64 %0, {%1, %1};" : "=l"(r) : "f"(x)); return r;
}
__device__ __forceinline__ void fma2(u64& d, u64 a, u64 b) {
    asm("fma.rn.f32x2 %0, %1, %2, %0;" : "+l"(d) : "l"(a), "l"(b));
}
__device__ __forceinline__ void mul2(u64& d, u64 a) {
    asm("mul.rn.f32x2 %0, %0, %1;" : "+l"(d) : "l"(a));
}
__device__ __forceinline__ float2 unpack2(u64 v) {
    float2 p; asm("mov.b64 {%0, %1}, %2;" : "=f"(p.x), "=f"(p.y) : "l"(v)); return p;
}

// Scratch (allocation-free: __device__ globals)
__device__ __align__(16) float g_QT[BB * HH * DD * SS];
__device__ __align__(16) float g_KT[BB * HH * DD * SS];
__device__ __align__(16) float g_V [BB * HH * SS * DD];

// ---------------------------------------------------------------------------
// Fused QKV projection GEMM (blockIdx.z selects Q/K/V).
// C[m,n] = sum_k X[m,k] * W[n,k] + bias[n];  M=8192, N=1024, K=1024.
// z=0: Q transposed [B,H,D,S] scaled 1/8; z=1: K transposed; z=2: V [B,H,S,D].
// ---------------------------------------------------------------------------
__global__ void __launch_bounds__(256) qkv_gemm_all(
    const float* __restrict__ X,
    const float* __restrict__ qw, const float* __restrict__ qb,
    const float* __restrict__ kw, const float* __restrict__ kb,
    const float* __restrict__ vw, const float* __restrict__ vb) {
    __shared__ float As[16][128];
    __shared__ float Bs[16][128];

    const int mode = blockIdx.z;
    const float* __restrict__ Wm = (mode == 0) ? qw : (mode == 1) ? kw : vw;
    const float* __restrict__ bias = (mode == 0) ? qb : (mode == 1) ? kb : vb;

    const int tid = threadIdx.x;
    const int m0 = blockIdx.y * 128;
    const int n0 = blockIdx.x * 128;
    const int tx = tid & 15;
    const int ty = tid >> 4;

    const int lr = tid >> 2;          // 0..63
    const int lc = (tid & 3) * 4;     // 0,4,8,12

    u64 acc[8][4];
#pragma unroll
    for (int i = 0; i < 8; i++)
#pragma unroll
        for (int j = 0; j < 4; j++) acc[i][j] = 0ull;

    for (int k0 = 0; k0 < EE; k0 += 16) {
        float4 a0 = *(const float4*)&X[(m0 + lr) * EE + k0 + lc];
        float4 a1 = *(const float4*)&X[(m0 + lr + 64) * EE + k0 + lc];
        float4 b0 = *(const float4*)&Wm[(n0 + lr) * EE + k0 + lc];
        float4 b1 = *(const float4*)&Wm[(n0 + lr + 64) * EE + k0 + lc];
        __syncthreads();
        As[lc + 0][lr] = a0.x; As[lc + 1][lr] = a0.y;
        As[lc + 2][lr] = a0.z; As[lc + 3][lr] = a0.w;
        As[lc + 0][lr + 64] = a1.x; As[lc + 1][lr + 64] = a1.y;
        As[lc + 2][lr + 64] = a1.z; As[lc + 3][lr + 64] = a1.w;
        Bs[lc + 0][lr] = b0.x; Bs[lc + 1][lr] = b0.y;
        Bs[lc + 2][lr] = b0.z; Bs[lc + 3][lr] = b0.w;
        Bs[lc + 0][lr + 64] = b1.x; Bs[lc + 1][lr + 64] = b1.y;
        Bs[lc + 2][lr + 64] = b1.z; Bs[lc + 3][lr + 64] = b1.w;
        __syncthreads();
#pragma unroll
        for (int kk = 0; kk < 16; ++kk) {
            // B pairs (contiguous n): 4 x f32x2
            ulonglong2 bq0 = *(const ulonglong2*)&Bs[kk][tx * 8];
            ulonglong2 bq1 = *(const ulonglong2*)&Bs[kk][tx * 8 + 4];
            u64 b2[4] = {bq0.x, bq0.y, bq1.x, bq1.y};
            // A scalars -> broadcast pairs
            float a_s[8];
            *(float4*)(a_s)     = *(float4*)&As[kk][ty * 8];
            *(float4*)(a_s + 4) = *(float4*)&As[kk][ty * 8 + 4];
            u64 a2[8];
#pragma unroll
            for (int i = 0; i < 8; i++) a2[i] = bcast2(a_s[i]);
#pragma unroll
            for (int i = 0; i < 8; i++)
#pragma unroll
                for (int j = 0; j < 4; j++) fma2(acc[i][j], a2[i], b2[j]);
        }
    }

#pragma unroll
    for (int i = 0; i < 8; i++) {
        const int row = m0 + ty * 8 + i;
        const int bb = row / SS;
        const int s = row % SS;
#pragma unroll
        for (int jp = 0; jp < 4; jp++) {
            float2 p = unpack2(acc[i][jp]);
#pragma unroll
            for (int half = 0; half < 2; half++) {
                const int n = n0 + tx * 8 + jp * 2 + half;
                float v = (half ? p.y : p.x) + bias[n];
                const int h = n >> 6;
                const int d = n & 63;
                if (mode == 0) {
                    g_QT[((bb * HH + h) * DD + d) * SS + s] = v * 0.125f;
                } else if (mode == 1) {
                    g_KT[((bb * HH + h) * DD + d) * SS + s] = v;
                } else {
                    g_V[((bb * HH + h) * SS + s) * DD + d] = v;
                }
            }
        }
    }
}

// ---------------------------------------------------------------------------
// Banded flash attention with packed f32x2 inner loops.
// ---------------------------------------------------------------------------
#define NQT (SS / 64)
#define PS_STRIDE 68
#define ATT_SMEM_FLOATS (4096 * 3 + 64 * PS_STRIDE + 64 + 64 + 64)
#define ATT_SMEM_BYTES (ATT_SMEM_FLOATS * 4)

__global__ void __launch_bounds__(256) banded_attn(const int* __restrict__ amask,
                                                   float* __restrict__ out) {
    extern __shared__ float sm[];
    float* Qs = sm;                 // [d][q]  64x64
    float* Ks = Qs + 4096;          // [d][k]  64x64
    float* Vs = Ks + 4096;          // [k][d]  64x64
    float* Ps = Vs + 4096;          // [k][q]  64x68 (padded)
    float* ms = Ps + 64 * PS_STRIDE;
    float* ls = ms + 64;
    float* fms = ls + 64;

    const int tid = threadIdx.x;
    const int qt = blockIdx.x % NQT;
    const int h = (blockIdx.x / NQT) % HH;
    const int b = blockIdx.x / (NQT * HH);
    const int q0 = qt * 64;
    const int bh = b * HH + h;
    const int tx = tid & 15;
    const int ty = tid >> 4;

    {
        const int c4 = tx * 4;
#pragma unroll
        for (int r = 0; r < 4; r++) {
            const int d = ty + r * 16;
            float4 v = *(const float4*)&g_QT[(bh * DD + d) * SS + q0 + c4];
            *(float4*)&Qs[d * 64 + c4] = v;
        }
    }
    if (tid < 64) { ms[tid] = -1e30f; ls[tid] = 0.f; }

    u64 o2[4][2];   // [query i][headdim pair]
#pragma unroll
    for (int i = 0; i < 4; i++) { o2[i][0] = 0ull; o2[i][1] = 0ull; }

    for (int kt = 0; kt < 9; ++kt) {
        const int j0 = q0 - WW + kt * 64;
        if (j0 + 64 <= 0 || j0 >= SS) continue;  // uniform skip
        __syncthreads();

        {
            const int c4 = tx * 4;
#pragma unroll
            for (int r = 0; r < 4; r++) {
                const int d = ty + r * 16;
                float kv0, kv1, kv2, kv3;
                int j = j0 + c4;
                kv0 = (j >= 0 && j < SS) ? g_KT[(bh * DD + d) * SS + j] : 0.f;
                kv1 = (j + 1 >= 0 && j + 1 < SS) ? g_KT[(bh * DD + d) * SS + j + 1] : 0.f;
                kv2 = (j + 2 >= 0 && j + 2 < SS) ? g_KT[(bh * DD + d) * SS + j + 2] : 0.f;
                kv3 = (j + 3 >= 0 && j + 3 < SS) ? g_KT[(bh * DD + d) * SS + j + 3] : 0.f;
                *(float4*)&Ks[d * 64 + c4] = make_float4(kv0, kv1, kv2, kv3);

                const int k = ty + r * 16;
                const int jv = j0 + k;
                float4 vv;
                if (jv >= 0 && jv < SS)
                    vv = *(const float4*)&g_V[(bh * SS + jv) * DD + c4];
                else
                    vv = make_float4(0.f, 0.f, 0.f, 0.f);
                *(float4*)&Vs[k * 64 + c4] = vv;
            }
            if (tid < 64) {
                const int j = j0 + tid;
                fms[tid] = (j >= 0 && j < SS && amask[b * SS + j] != 0) ? -10000.f : 0.f;
            }
        }
        __syncthreads();

        // Scores: S[q][k] = Q . K, packed along k
        u64 s2[4][2];
#pragma unroll
        for (int i = 0; i < 4; i++) { s2[i][0] = 0ull; s2[i][1] = 0ull; }

#pragma unroll 8
        for (int d = 0; d < 64; ++d) {
            ulonglong2 kq = *(const ulonglong2*)&Ks[d * 64 + tx * 4];
            float4 q4 = *(float4*)&Qs[d * 64 + ty * 4];
            u64 qb0 = bcast2(q4.x), qb1 = bcast2(q4.y);
            u64 qb2 = bcast2(q4.z), qb3 = bcast2(q4.w);
            fma2(s2[0][0], qb0, kq.x); fma2(s2[0][1], qb0, kq.y);
            fma2(s2[1][0], qb1, kq.x); fma2(s2[1][1], qb1, kq.y);
            fma2(s2[2][0], qb2, kq.x); fma2(s2[2][1], qb2, kq.y);
            fma2(s2[3][0], qb3, kq.x); fma2(s2[3][1], qb3, kq.y);
        }

        // Mask + online softmax update
        float mloc[4], fscale[4], rsum[4];
#pragma unroll
        for (int ii = 0; ii < 4; ++ii) {
            const int i = q0 + ty * 4 + ii;
            float svr[4];
            {
                float2 pa = unpack2(s2[ii][0]);
                float2 pb = unpack2(s2[ii][1]);
                svr[0] = pa.x; svr[1] = pa.y; svr[2] = pb.x; svr[3] = pb.y;
            }
            float rm = -INFINITY;
#pragma unroll
            for (int jj = 0; jj < 4; jj++) {
                const int j = j0 + tx * 4 + jj;
                const bool valid = (j >= 0) && (j < SS) && (j - i <= WW) && (i - j <= WW);
                const float sv = valid ? svr[jj] + fms[tx * 4 + jj] : -INFINITY;
                svr[jj] = sv;
                rm = fmaxf(rm, sv);
            }
#pragma unroll
            for (int off = 1; off < 16; off <<= 1)
                rm = fmaxf(rm, __shfl_xor_sync(0xffffffffu, rm, off));
            const float mo = ms[ty * 4 + ii];
            const float mn = fmaxf(mo, rm);
            mloc[ii] = mn;
            fscale[ii] = __expf(mo - mn);
            float rs = 0.f;
#pragma unroll
            for (int jj = 0; jj < 4; jj++) {
                const float pv = __expf(svr[jj] - mn);
                rs += pv;
                Ps[(tx * 4 + jj) * PS_STRIDE + ty * 4 + ii] = pv;
            }
#pragma unroll
            for (int off = 1; off < 16; off <<= 1)
                rs += __shfl_xor_sync(0xffffffffu, rs, off);
            rsum[ii] = rs;
            u64 fsb = bcast2(fscale[ii]);
            mul2(o2[ii][0], fsb);
            mul2(o2[ii][1], fsb);
        }
        __syncthreads();
        if (tx == 0) {
#pragma unroll
            for (int ii = 0; ii < 4; ii++) {
                const int ql = ty * 4 + ii;
                ms[ql] = mloc[ii];
                ls[ql] = ls[ql] * fscale[ii] + rsum[ii];
            }
        }

        // O += P . V, packed along headdim
#pragma unroll 8
        for (int k = 0; k < 64; ++k) {
            ulonglong2 vq = *(const ulonglong2*)&Vs[k * 64 + tx * 4];
            float4 p4 = *(float4*)&Ps[k * PS_STRIDE + ty * 4];
            u64 pb0 = bcast2(p4.x), pb1 = bcast2(p4.y);
            u64 pb2 = bcast2(p4.z), pb3 = bcast2(p4.w);
            fma2(o2[0][0], pb0, vq.x); fma2(o2[0][1], pb0, vq.y);
            fma2(o2[1][0], pb1, vq.x); fma2(o2[1][1], pb1, vq.y);
            fma2(o2[2][0], pb2, vq.x); fma2(o2[2][1], pb2, vq.y);
            fma2(o2[3][0], pb3, vq.x); fma2(o2[3][1], pb3, vq.y);
        }
    }

    __syncthreads();
#pragma unroll
    for (int ii = 0; ii < 4; ii++) {
        const float inv = 1.f / ls[ty * 4 + ii];
        const int i = q0 + ty * 4 + ii;
        float2 pa = unpack2(o2[ii][0]);
        float2 pb = unpack2(o2[ii][1]);
        float4 ov = make_float4(pa.x * inv, pa.y * inv, pb.x * inv, pb.y * inv);
        *(float4*)&out[(b * SS + i) * EE + h * 64 + tx * 4] = ov;
    }
}

// ---------------------------------------------------------------------------
extern "C" void kernel_launch(void* const* d_in, const int* in_sizes, int n_in,
                              void* d_out, int out_size) {
    const float* hs   = (const float*)d_in[0];
    const int*   am   = (const int*)d_in[1];
    const float* q_w  = (const float*)d_in[2];
    const float* q_b  = (const float*)d_in[3];
    const float* k_w  = (const float*)d_in[4];
    const float* k_b  = (const float*)d_in[5];
    const float* v_w  = (const float*)d_in[6];
    const float* v_b  = (const float*)d_in[7];
    float* out = (float*)d_out;

    cudaFuncSetAttribute(banded_attn, cudaFuncAttributeMaxDynamicSharedMemorySize,
                         ATT_SMEM_BYTES);

    dim3 g(EE / 128, (BB * SS) / 128, 3);  // (8, 64, 3)
    qkv_gemm_all<<<g, 256>>>(hs, q_w, q_b, k_w, k_b, v_w, v_b);

    banded_attn<<<BB * HH * NQT, 256, ATT_SMEM_BYTES>>>(am, out);
}

// round 4
// speedup vs baseline: 1.9220x; 1.8296x over previous
#include <cuda_runtime.h>
#include <cuda_bf16.h>
#include <cstdint>
#include <math.h>

#define BB 2
#define SS 4096
#define EE 1024
#define HH 16
#define DD 64
#define WW 256

#define MT 128
#define NT 128
#define NTOT 3072
#define NCHUNK 48

typedef unsigned long long u64;

// ---------------- scratch (__device__ globals, no allocs) -------------------
__device__ __align__(16) float g_QT[BB * HH * DD * SS];
__device__ __align__(16) float g_KT[BB * HH * DD * SS];
__device__ __align__(16) float g_V [BB * HH * SS * DD];
__device__ __align__(16) __nv_bfloat16 g_Xh[BB * SS * EE];
__device__ __align__(16) __nv_bfloat16 g_Xl[BB * SS * EE];
__device__ __align__(16) __nv_bfloat16 g_Wh[NTOT * EE];
__device__ __align__(16) __nv_bfloat16 g_Wl[NTOT * EE];

// ---------------- PTX helpers ----------------------------------------------
__device__ __forceinline__ uint32_t smem_u32(const void* p) {
    uint32_t a;
    asm("{ .reg .u64 t; cvta.to.shared.u64 t, %1; cvt.u32.u64 %0, t; }" : "=r"(a) : "l"(p));
    return a;
}
#define SWZ(o) ((o) ^ (((o) >> 3) & 0x70))

__device__ __forceinline__ void cp16(uint32_t s, const void* g) {
    asm volatile("cp.async.cg.shared.global [%0], [%1], 16;" :: "r"(s), "l"(g));
}
#define CP_COMMIT() asm volatile("cp.async.commit_group;" ::: "memory")
#define CP_WAIT1()  asm volatile("cp.async.wait_group 1;" ::: "memory")

__device__ __forceinline__ void ldsm4(uint32_t* r, uint32_t addr) {
    asm volatile("ldmatrix.sync.aligned.m8n8.x4.shared.b16 {%0,%1,%2,%3}, [%4];"
                 : "=r"(r[0]), "=r"(r[1]), "=r"(r[2]), "=r"(r[3]) : "r"(addr));
}
__device__ __forceinline__ void mma16816(float* c, const uint32_t* a, uint32_t b0, uint32_t b1) {
    asm volatile("mma.sync.aligned.m16n8k16.row.col.f32.bf16.bf16.f32 "
                 "{%0,%1,%2,%3}, {%4,%5,%6,%7}, {%8,%9}, {%0,%1,%2,%3};"
                 : "+f"(c[0]), "+f"(c[1]), "+f"(c[2]), "+f"(c[3])
                 : "r"(a[0]), "r"(a[1]), "r"(a[2]), "r"(a[3]), "r"(b0), "r"(b1));
}

// ---------------- split-prep kernels ---------------------------------------
union BF4 { __nv_bfloat16 b[4]; uint2 u; };

__global__ void __launch_bounds__(256) split_x(const float* __restrict__ X) {
    size_t i = ((size_t)blockIdx.x * 256 + threadIdx.x) * 4;
    float4 v = *(const float4*)(X + i);
    BF4 h, l;
    float vv[4] = {v.x, v.y, v.z, v.w};
#pragma unroll
    for (int j = 0; j < 4; j++) {
        h.b[j] = __float2bfloat16(vv[j]);
        l.b[j] = __float2bfloat16(vv[j] - __bfloat162float(h.b[j]));
    }
    *(uint2*)&g_Xh[i] = h.u;
    *(uint2*)&g_Xl[i] = l.u;
}

__global__ void __launch_bounds__(256) split_w(const float* __restrict__ qw,
                                               const float* __restrict__ kw,
                                               const float* __restrict__ vw) {
    size_t i = ((size_t)blockIdx.x * 256 + threadIdx.x) * 4;
    int proj = (int)(i >> 20);
    const float* W = (proj == 0) ? qw : (proj == 1) ? kw : vw;
    size_t loc = i & ((1u << 20) - 1);
    float4 v = *(const float4*)(W + loc);
    BF4 h, l;
    float vv[4] = {v.x, v.y, v.z, v.w};
#pragma unroll
    for (int j = 0; j < 4; j++) {
        h.b[j] = __float2bfloat16(vv[j]);
        l.b[j] = __float2bfloat16(vv[j] - __bfloat162float(h.b[j]));
    }
    *(uint2*)&g_Wh[i] = h.u;
    *(uint2*)&g_Wl[i] = l.u;
}

// ---------------- HMMA QKV GEMM --------------------------------------------
// SMEM: stage s: A @ s*32768 (16KB), B @ s*32768+16384 (16KB). 64KB stages.
// Epilogue reuses smem as fp32 C[128][132] = 67584 B.
#define GEMM_SMEM 67584

__device__ __forceinline__ void issue_loads(uint32_t sb, int stage, int chunk,
                                            int m0, int n0, int tid) {
    const int seg = chunk >> 4;
    const int kc = (chunk & 15) * 64;
    const __nv_bfloat16* A = (seg == 2) ? g_Xl : g_Xh;
    const __nv_bfloat16* Bw = (seg == 1) ? g_Wl : g_Wh;
    const uint32_t Ab = sb + stage * 32768;
    const uint32_t Bb = Ab + 16384;
#pragma unroll
    for (int i = 0; i < 4; i++) {
        int u = tid + i * 256;
        int r = u >> 3, p = u & 7;
        cp16(Ab + SWZ(r * 128 + p * 16), (const void*)(A + (size_t)(m0 + r) * EE + kc + p * 8));
        cp16(Bb + SWZ(r * 128 + p * 16), (const void*)(Bw + (size_t)(n0 + r) * EE + kc + p * 8));
    }
}

__global__ void __launch_bounds__(256) qkv_hmma_gemm(const float* __restrict__ qb,
                                                     const float* __restrict__ kb,
                                                     const float* __restrict__ vb) {
    extern __shared__ char smraw[];
    const uint32_t sb = smem_u32(smraw);
    const int tid = threadIdx.x;
    const int wid = tid >> 5;
    const int lane = tid & 31;
    const int n0 = blockIdx.x * NT;
    const int m0 = blockIdx.y * MT;

    const int warpRow = (wid & 1) * 64;   // 2 warps along M
    const int warpCol = (wid >> 1) * 32;  // 4 warps along N

    const int lrow = lane & 15;
    const int lsel = (lane >> 4) * 16;

    float acc[4][4][4];
#pragma unroll
    for (int mi = 0; mi < 4; mi++)
#pragma unroll
        for (int ni = 0; ni < 4; ni++)
#pragma unroll
            for (int r = 0; r < 4; r++) acc[mi][ni][r] = 0.f;

    issue_loads(sb, 0, 0, m0, n0, tid); CP_COMMIT();
    issue_loads(sb, 1, 1, m0, n0, tid); CP_COMMIT();

    for (int c = 0; c < NCHUNK; c++) {
        const int s = c & 1;
        CP_WAIT1();
        __syncthreads();
        const uint32_t Ab = sb + s * 32768;
        const uint32_t Bb = Ab + 16384;
#pragma unroll
        for (int kk = 0; kk < 4; kk++) {
            uint32_t afr[4][4];
#pragma unroll
            for (int mi = 0; mi < 4; mi++) {
                uint32_t o = (warpRow + mi * 16 + lrow) * 128 + kk * 32 + lsel;
                ldsm4(afr[mi], Ab + SWZ(o));
            }
            uint32_t bfr[2][4];
#pragma unroll
            for (int bi = 0; bi < 2; bi++) {
                uint32_t o = (warpCol + bi * 16 + lrow) * 128 + kk * 32 + lsel;
                ldsm4(bfr[bi], Bb + SWZ(o));
            }
#pragma unroll
            for (int mi = 0; mi < 4; mi++)
#pragma unroll
                for (int ni = 0; ni < 4; ni++)
                    mma16816(acc[mi][ni], afr[mi],
                             bfr[ni >> 1][ni & 1], bfr[ni >> 1][(ni & 1) + 2]);
        }
        __syncthreads();
        if (c + 2 < NCHUNK) issue_loads(sb, s, c + 2, m0, n0, tid);
        CP_COMMIT();
    }
    __syncthreads();

    // -------- epilogue: stage C in smem, then bias + layout transform -------
    float* Cs = (float*)smraw;   // [128][132]
#pragma unroll
    for (int mi = 0; mi < 4; mi++)
#pragma unroll
        for (int ni = 0; ni < 4; ni++) {
            const int r = warpRow + mi * 16 + (lane >> 2);
            const int col = warpCol + ni * 8 + (lane & 3) * 2;
            Cs[r * 132 + col]       = acc[mi][ni][0];
            Cs[r * 132 + col + 1]   = acc[mi][ni][1];
            Cs[(r + 8) * 132 + col]     = acc[mi][ni][2];
            Cs[(r + 8) * 132 + col + 1] = acc[mi][ni][3];
        }
    __syncthreads();

    const int proj = n0 >> 10;
    const int nb1023 = n0 & 1023;
    const int h0 = nb1023 >> 6;
    const int b = m0 >> 12;
    const int s_base = m0 & (SS - 1);

    if (proj < 2) {
        float* dst = (proj == 0) ? g_QT : g_KT;
        const float* bp = (proj == 0) ? qb : kb;
        const float scale = (proj == 0) ? 0.125f : 1.0f;
#pragma unroll
        for (int it = 0; it < 16; it++) {
            const int id = tid + it * 256;
            const int s4 = (id & 31) * 4;
            const int col = id >> 5;
            const float bv = bp[nb1023 + col];
            const int h = h0 + (col >> 6);
            const int d = col & 63;
            float4 v;
            v.x = (Cs[(s4 + 0) * 132 + col] + bv) * scale;
            v.y = (Cs[(s4 + 1) * 132 + col] + bv) * scale;
            v.z = (Cs[(s4 + 2) * 132 + col] + bv) * scale;
            v.w = (Cs[(s4 + 3) * 132 + col] + bv) * scale;
            *(float4*)&dst[((b * HH + h) * DD + d) * SS + s_base + s4] = v;
        }
    } else {
#pragma unroll
        for (int it = 0; it < 16; it++) {
            const int id = tid + it * 256;
            const int col = (id & 31) * 4;
            const int s = id >> 5;
            const int h = h0 + (col >> 6);
            const int d = col & 63;
            float4 v = *(float4*)&Cs[s * 132 + col];
            v.x += vb[nb1023 + col];
            v.y += vb[nb1023 + col + 1];
            v.z += vb[nb1023 + col + 2];
            v.w += vb[nb1023 + col + 3];
            *(float4*)&g_V[((b * HH + h) * SS + s_base + s) * DD + d] = v;
        }
    }
}

// ---------------- banded flash attention (fp32, unchanged) ------------------
__device__ __forceinline__ u64 bcast2(float x) {
    u64 r; asm("mov.b64 %0, {%1, %1};" : "=l"(r) : "f"(x)); return r;
}
__device__ __forceinline__ void fma2(u64& d, u64 a, u64 b) {
    asm("fma.rn.f32x2 %0, %1, %2, %0;" : "+l"(d) : "l"(a), "l"(b));
}
__device__ __forceinline__ void mul2(u64& d, u64 a) {
    asm("mul.rn.f32x2 %0, %0, %1;" : "+l"(d) : "l"(a));
}
__device__ __forceinline__ float2 unpack2(u64 v) {
    float2 p; asm("mov.b64 {%0, %1}, %2;" : "=f"(p.x), "=f"(p.y) : "l"(v)); return p;
}

#define NQT (SS / 64)
#define PS_STRIDE 68
#define ATT_SMEM_FLOATS (4096 * 3 + 64 * PS_STRIDE + 64 + 64 + 64)
#define ATT_SMEM_BYTES (ATT_SMEM_FLOATS * 4)

__global__ void __launch_bounds__(256) banded_attn(const int* __restrict__ amask,
                                                   float* __restrict__ out) {
    extern __shared__ float sm[];
    float* Qs = sm;
    float* Ks = Qs + 4096;
    float* Vs = Ks + 4096;
    float* Ps = Vs + 4096;
    float* ms = Ps + 64 * PS_STRIDE;
    float* ls = ms + 64;
    float* fms = ls + 64;

    const int tid = threadIdx.x;
    const int qt = blockIdx.x % NQT;
    const int h = (blockIdx.x / NQT) % HH;
    const int b = blockIdx.x / (NQT * HH);
    const int q0 = qt * 64;
    const int bh = b * HH + h;
    const int tx = tid & 15;
    const int ty = tid >> 4;

    {
        const int c4 = tx * 4;
#pragma unroll
        for (int r = 0; r < 4; r++) {
            const int d = ty + r * 16;
            float4 v = *(const float4*)&g_QT[(bh * DD + d) * SS + q0 + c4];
            *(float4*)&Qs[d * 64 + c4] = v;
        }
    }
    if (tid < 64) { ms[tid] = -1e30f; ls[tid] = 0.f; }

    u64 o2[4][2];
#pragma unroll
    for (int i = 0; i < 4; i++) { o2[i][0] = 0ull; o2[i][1] = 0ull; }

    for (int kt = 0; kt < 9; ++kt) {
        const int j0 = q0 - WW + kt * 64;
        if (j0 + 64 <= 0 || j0 >= SS) continue;
        __syncthreads();

        {
            const int c4 = tx * 4;
#pragma unroll
            for (int r = 0; r < 4; r++) {
                const int d = ty + r * 16;
                float kv0, kv1, kv2, kv3;
                int j = j0 + c4;
                kv0 = (j >= 0 && j < SS) ? g_KT[(bh * DD + d) * SS + j] : 0.f;
                kv1 = (j + 1 >= 0 && j + 1 < SS) ? g_KT[(bh * DD + d) * SS + j + 1] : 0.f;
                kv2 = (j + 2 >= 0 && j + 2 < SS) ? g_KT[(bh * DD + d) * SS + j + 2] : 0.f;
                kv3 = (j + 3 >= 0 && j + 3 < SS) ? g_KT[(bh * DD + d) * SS + j + 3] : 0.f;
                *(float4*)&Ks[d * 64 + c4] = make_float4(kv0, kv1, kv2, kv3);

                const int k = ty + r * 16;
                const int jv = j0 + k;
                float4 vv;
                if (jv >= 0 && jv < SS)
                    vv = *(const float4*)&g_V[(bh * SS + jv) * DD + c4];
                else
                    vv = make_float4(0.f, 0.f, 0.f, 0.f);
                *(float4*)&Vs[k * 64 + c4] = vv;
            }
            if (tid < 64) {
                const int j = j0 + tid;
                fms[tid] = (j >= 0 && j < SS && amask[b * SS + j] != 0) ? -10000.f : 0.f;
            }
        }
        __syncthreads();

        u64 s2[4][2];
#pragma unroll
        for (int i = 0; i < 4; i++) { s2[i][0] = 0ull; s2[i][1] = 0ull; }

#pragma unroll 8
        for (int d = 0; d < 64; ++d) {
            ulonglong2 kq = *(const ulonglong2*)&Ks[d * 64 + tx * 4];
            float4 q4 = *(float4*)&Qs[d * 64 + ty * 4];
            u64 qb0 = bcast2(q4.x), qb1 = bcast2(q4.y);
            u64 qb2 = bcast2(q4.z), qb3 = bcast2(q4.w);
            fma2(s2[0][0], qb0, kq.x); fma2(s2[0][1], qb0, kq.y);
            fma2(s2[1][0], qb1, kq.x); fma2(s2[1][1], qb1, kq.y);
            fma2(s2[2][0], qb2, kq.x); fma2(s2[2][1], qb2, kq.y);
            fma2(s2[3][0], qb3, kq.x); fma2(s2[3][1], qb3, kq.y);
        }

        float mloc[4], fscale[4], rsum[4];
#pragma unroll
        for (int ii = 0; ii < 4; ++ii) {
            const int i = q0 + ty * 4 + ii;
            float svr[4];
            {
                float2 pa = unpack2(s2[ii][0]);
                float2 pb = unpack2(s2[ii][1]);
                svr[0] = pa.x; svr[1] = pa.y; svr[2] = pb.x; svr[3] = pb.y;
            }
            float rm = -INFINITY;
#pragma unroll
            for (int jj = 0; jj < 4; jj++) {
                const int j = j0 + tx * 4 + jj;
                const bool valid = (j >= 0) && (j < SS) && (j - i <= WW) && (i - j <= WW);
                const float sv = valid ? svr[jj] + fms[tx * 4 + jj] : -INFINITY;
                svr[jj] = sv;
                rm = fmaxf(rm, sv);
            }
#pragma unroll
            for (int off = 1; off < 16; off <<= 1)
                rm = fmaxf(rm, __shfl_xor_sync(0xffffffffu, rm, off));
            const float mo = ms[ty * 4 + ii];
            const float mn = fmaxf(mo, rm);
            mloc[ii] = mn;
            fscale[ii] = __expf(mo - mn);
            float rs = 0.f;
#pragma unroll
            for (int jj = 0; jj < 4; jj++) {
                const float pv = __expf(svr[jj] - mn);
                rs += pv;
                Ps[(tx * 4 + jj) * PS_STRIDE + ty * 4 + ii] = pv;
            }
#pragma unroll
            for (int off = 1; off < 16; off <<= 1)
                rs += __shfl_xor_sync(0xffffffffu, rs, off);
            rsum[ii] = rs;
            u64 fsb = bcast2(fscale[ii]);
            mul2(o2[ii][0], fsb);
            mul2(o2[ii][1], fsb);
        }
        __syncthreads();
        if (tx == 0) {
#pragma unroll
            for (int ii = 0; ii < 4; ii++) {
                const int ql = ty * 4 + ii;
                ms[ql] = mloc[ii];
                ls[ql] = ls[ql] * fscale[ii] + rsum[ii];
            }
        }

#pragma unroll 8
        for (int k = 0; k < 64; ++k) {
            ulonglong2 vq = *(const ulonglong2*)&Vs[k * 64 + tx * 4];
            float4 p4 = *(float4*)&Ps[k * PS_STRIDE + ty * 4];
            u64 pb0 = bcast2(p4.x), pb1 = bcast2(p4.y);
            u64 pb2 = bcast2(p4.z), pb3 = bcast2(p4.w);
            fma2(o2[0][0], pb0, vq.x); fma2(o2[0][1], pb0, vq.y);
            fma2(o2[1][0], pb1, vq.x); fma2(o2[1][1], pb1, vq.y);
            fma2(o2[2][0], pb2, vq.x); fma2(o2[2][1], pb2, vq.y);
            fma2(o2[3][0], pb3, vq.x); fma2(o2[3][1], pb3, vq.y);
        }
    }

    __syncthreads();
#pragma unroll
    for (int ii = 0; ii < 4; ii++) {
        const float inv = 1.f / ls[ty * 4 + ii];
        const int i = q0 + ty * 4 + ii;
        float2 pa = unpack2(o2[ii][0]);
        float2 pb = unpack2(o2[ii][1]);
        float4 ov = make_float4(pa.x * inv, pa.y * inv, pb.x * inv, pb.y * inv);
        *(float4*)&out[(b * SS + i) * EE + h * 64 + tx * 4] = ov;
    }
}

// ---------------------------------------------------------------------------
extern "C" void kernel_launch(void* const* d_in, const int* in_sizes, int n_in,
                              void* d_out, int out_size) {
    const float* hs  = (const float*)d_in[0];
    const int*   am  = (const int*)d_in[1];
    const float* q_w = (const float*)d_in[2];
    const float* q_b = (const float*)d_in[3];
    const float* k_w = (const float*)d_in[4];
    const float* k_b = (const float*)d_in[5];
    const float* v_w = (const float*)d_in[6];
    const float* v_b = (const float*)d_in[7];
    float* out = (float*)d_out;

    cudaFuncSetAttribute(qkv_hmma_gemm, cudaFuncAttributeMaxDynamicSharedMemorySize,
                         GEMM_SMEM);
    cudaFuncSetAttribute(banded_attn, cudaFuncAttributeMaxDynamicSharedMemorySize,
                         ATT_SMEM_BYTES);

    split_x<<<(BB * SS * EE) / 1024, 256>>>(hs);
    split_w<<<(3 * EE * EE) / 1024, 256>>>(q_w, k_w, v_w);

    dim3 g(NTOT / NT, (BB * SS) / MT);   // (24, 64)
    qkv_hmma_gemm<<<g, 256, GEMM_SMEM>>>(q_b, k_b, v_b);

    banded_attn<<<BB * HH * NQT, 256, ATT_SMEM_BYTES>>>(am, out);
}

// round 6
// speedup vs baseline: 3.5192x; 1.8310x over previous
#include <cuda_runtime.h>
#include <cuda_bf16.h>
#include <cuda_fp16.h>
#include <cstdint>
#include <math.h>

#define BB 2
#define SS 4096
#define EE 1024
#define HH 16
#define DD 64
#define WW 256

#define MT 128
#define NT 128
#define NTOT 3072
#define NCHUNK 48

typedef unsigned long long u64;

// ---------------- scratch (__device__ globals, no allocs) -------------------
__device__ __align__(16) __half g_Qb[BB * HH * SS * DD];  // [B,H,S,D] fp16
__device__ __align__(16) __half g_Kb[BB * HH * SS * DD];  // [B,H,S,D] fp16
__device__ __align__(16) __half g_VT[BB * HH * DD * SS];  // [B,H,D,S] fp16
__device__ __align__(16) __nv_bfloat16 g_Xh[BB * SS * EE];
__device__ __align__(16) __nv_bfloat16 g_Xl[BB * SS * EE];
__device__ __align__(16) __nv_bfloat16 g_Wh[NTOT * EE];
__device__ __align__(16) __nv_bfloat16 g_Wl[NTOT * EE];

// ---------------- PTX helpers ----------------------------------------------
__device__ __forceinline__ uint32_t smem_u32(const void* p) {
    uint32_t a;
    asm("{ .reg .u64 t; cvta.to.shared.u64 t, %1; cvt.u32.u64 %0, t; }" : "=r"(a) : "l"(p));
    return a;
}
#define SWZ(o) ((o) ^ (((o) >> 3) & 0x70))

__device__ __forceinline__ void cp16(uint32_t s, const void* g) {
    asm volatile("cp.async.cg.shared.global [%0], [%1], 16;" :: "r"(s), "l"(g));
}
#define CP_COMMIT() asm volatile("cp.async.commit_group;" ::: "memory")
#define CP_WAIT1()  asm volatile("cp.async.wait_group 1;" ::: "memory")

__device__ __forceinline__ void ldsm4(uint32_t* r, uint32_t addr) {
    asm volatile("ldmatrix.sync.aligned.m8n8.x4.shared.b16 {%0,%1,%2,%3}, [%4];"
                 : "=r"(r[0]), "=r"(r[1]), "=r"(r[2]), "=r"(r[3]) : "r"(addr));
}
__device__ __forceinline__ void mma16816(float* c, const uint32_t* a, uint32_t b0, uint32_t b1) {
    asm volatile("mma.sync.aligned.m16n8k16.row.col.f32.bf16.bf16.f32 "
                 "{%0,%1,%2,%3}, {%4,%5,%6,%7}, {%8,%9}, {%0,%1,%2,%3};"
                 : "+f"(c[0]), "+f"(c[1]), "+f"(c[2]), "+f"(c[3])
                 : "r"(a[0]), "r"(a[1]), "r"(a[2]), "r"(a[3]), "r"(b0), "r"(b1));
}
__device__ __forceinline__ void mma16816h(float* c, const uint32_t* a, uint32_t b0, uint32_t b1) {
    asm volatile("mma.sync.aligned.m16n8k16.row.col.f32.f16.f16.f32 "
                 "{%0,%1,%2,%3}, {%4,%5,%6,%7}, {%8,%9}, {%0,%1,%2,%3};"
                 : "+f"(c[0]), "+f"(c[1]), "+f"(c[2]), "+f"(c[3])
                 : "r"(a[0]), "r"(a[1]), "r"(a[2]), "r"(a[3]), "r"(b0), "r"(b1));
}
__device__ __forceinline__ uint32_t packbf2(float lo, float hi) {
    uint32_t r;
    asm("cvt.rn.bf16x2.f32 %0, %1, %2;" : "=r"(r) : "f"(hi), "f"(lo));
    return r;
}
__device__ __forceinline__ uint32_t packh2(float lo, float hi) {
    uint32_t r;
    asm("cvt.rn.f16x2.f32 %0, %1, %2;" : "=r"(r) : "f"(hi), "f"(lo));
    return r;
}

// ---------------- split-prep kernels ---------------------------------------
union BF4 { __nv_bfloat16 b[4]; uint2 u; };

__global__ void __launch_bounds__(256) split_x(const float* __restrict__ X) {
    size_t i = ((size_t)blockIdx.x * 256 + threadIdx.x) * 4;
    float4 v = *(const float4*)(X + i);
    BF4 h, l;
    float vv[4] = {v.x, v.y, v.z, v.w};
#pragma unroll
    for (int j = 0; j < 4; j++) {
        h.b[j] = __float2bfloat16(vv[j]);
        l.b[j] = __float2bfloat16(vv[j] - __bfloat162float(h.b[j]));
    }
    *(uint2*)&g_Xh[i] = h.u;
    *(uint2*)&g_Xl[i] = l.u;
}

__global__ void __launch_bounds__(256) split_w(const float* __restrict__ qw,
                                               const float* __restrict__ kw,
                                               const float* __restrict__ vw) {
    size_t i = ((size_t)blockIdx.x * 256 + threadIdx.x) * 4;
    int proj = (int)(i >> 20);
    const float* W = (proj == 0) ? qw : (proj == 1) ? kw : vw;
    size_t loc = i & ((1u << 20) - 1);
    float4 v = *(const float4*)(W + loc);
    BF4 h, l;
    float vv[4] = {v.x, v.y, v.z, v.w};
#pragma unroll
    for (int j = 0; j < 4; j++) {
        h.b[j] = __float2bfloat16(vv[j]);
        l.b[j] = __float2bfloat16(vv[j] - __bfloat162float(h.b[j]));
    }
    *(uint2*)&g_Wh[i] = h.u;
    *(uint2*)&g_Wl[i] = l.u;
}

// ---------------- HMMA QKV GEMM --------------------------------------------
#define GEMM_SMEM 67584

__device__ __forceinline__ void issue_loads(uint32_t sb, int stage, int chunk,
                                            int m0, int n0, int tid) {
    const int seg = chunk >> 4;
    const int kc = (chunk & 15) * 64;
    const __nv_bfloat16* A = (seg == 2) ? g_Xl : g_Xh;
    const __nv_bfloat16* Bw = (seg == 1) ? g_Wl : g_Wh;
    const uint32_t Ab = sb + stage * 32768;
    const uint32_t Bb = Ab + 16384;
#pragma unroll
    for (int i = 0; i < 4; i++) {
        int u = tid + i * 256;
        int r = u >> 3, p = u & 7;
        cp16(Ab + SWZ(r * 128 + p * 16), (const void*)(A + (size_t)(m0 + r) * EE + kc + p * 8));
        cp16(Bb + SWZ(r * 128 + p * 16), (const void*)(Bw + (size_t)(n0 + r) * EE + kc + p * 8));
    }
}

__global__ void __launch_bounds__(256) qkv_hmma_gemm(const float* __restrict__ qb,
                                                     const float* __restrict__ kb,
                                                     const float* __restrict__ vb) {
    extern __shared__ char smraw[];
    const uint32_t sb = smem_u32(smraw);
    const int tid = threadIdx.x;
    const int wid = tid >> 5;
    const int lane = tid & 31;
    const int n0 = blockIdx.x * NT;
    const int m0 = blockIdx.y * MT;

    const int warpRow = (wid & 1) * 64;
    const int warpCol = (wid >> 1) * 32;
    const int lrow = lane & 15;
    const int lsel = (lane >> 4) * 16;

    float acc[4][4][4];
#pragma unroll
    for (int mi = 0; mi < 4; mi++)
#pragma unroll
        for (int ni = 0; ni < 4; ni++)
#pragma unroll
            for (int r = 0; r < 4; r++) acc[mi][ni][r] = 0.f;

    issue_loads(sb, 0, 0, m0, n0, tid); CP_COMMIT();
    issue_loads(sb, 1, 1, m0, n0, tid); CP_COMMIT();

    for (int c = 0; c < NCHUNK; c++) {
        const int s = c & 1;
        CP_WAIT1();
        __syncthreads();
        const uint32_t Ab = sb + s * 32768;
        const uint32_t Bb = Ab + 16384;
#pragma unroll
        for (int kk = 0; kk < 4; kk++) {
            uint32_t afr[4][4];
#pragma unroll
            for (int mi = 0; mi < 4; mi++) {
                uint32_t o = (warpRow + mi * 16 + lrow) * 128 + kk * 32 + lsel;
                ldsm4(afr[mi], Ab + SWZ(o));
            }
            uint32_t bfr[2][4];
#pragma unroll
            for (int bi = 0; bi < 2; bi++) {
                uint32_t o = (warpCol + bi * 16 + lrow) * 128 + kk * 32 + lsel;
                ldsm4(bfr[bi], Bb + SWZ(o));
            }
#pragma unroll
            for (int mi = 0; mi < 4; mi++)
#pragma unroll
                for (int ni = 0; ni < 4; ni++)
                    mma16816(acc[mi][ni], afr[mi],
                             bfr[ni >> 1][ni & 1], bfr[ni >> 1][(ni & 1) + 2]);
        }
        __syncthreads();
        if (c + 2 < NCHUNK) issue_loads(sb, s, c + 2, m0, n0, tid);
        CP_COMMIT();
    }
    __syncthreads();

    // -------- epilogue: stage C in smem, bias + fp16 + layout transform -----
    float* Cs = (float*)smraw;   // [128][132]
#pragma unroll
    for (int mi = 0; mi < 4; mi++)
#pragma unroll
        for (int ni = 0; ni < 4; ni++) {
            const int r = warpRow + mi * 16 + (lane >> 2);
            const int col = warpCol + ni * 8 + (lane & 3) * 2;
            Cs[r * 132 + col]       = acc[mi][ni][0];
            Cs[r * 132 + col + 1]   = acc[mi][ni][1];
            Cs[(r + 8) * 132 + col]     = acc[mi][ni][2];
            Cs[(r + 8) * 132 + col + 1] = acc[mi][ni][3];
        }
    __syncthreads();

    const int proj = n0 >> 10;
    const int nb1023 = n0 & 1023;
    const int h0 = nb1023 >> 6;
    const int b = m0 >> 12;
    const int s_base = m0 & (SS - 1);

    if (proj < 2) {
        __half* dst = (proj == 0) ? g_Qb : g_Kb;
        const float* bp = (proj == 0) ? qb : kb;
        const float scale = (proj == 0) ? 0.125f : 1.0f;
#pragma unroll
        for (int it = 0; it < 16; it++) {
            const int id = tid + it * 256;
            const int col = (id & 31) * 4;
            const int s = id >> 5;
            const int h = h0 + (col >> 6);
            const int d = col & 63;
            float v0 = (Cs[s * 132 + col]     + bp[nb1023 + col])     * scale;
            float v1 = (Cs[s * 132 + col + 1] + bp[nb1023 + col + 1]) * scale;
            float v2 = (Cs[s * 132 + col + 2] + bp[nb1023 + col + 2]) * scale;
            float v3 = (Cs[s * 132 + col + 3] + bp[nb1023 + col + 3]) * scale;
            uint2 pk;
            pk.x = packh2(v0, v1);
            pk.y = packh2(v2, v3);
            *(uint2*)&dst[((size_t)(b * HH + h) * SS + s_base + s) * DD + d] = pk;
        }
    } else {
#pragma unroll
        for (int it = 0; it < 16; it++) {
            const int id = tid + it * 256;
            const int col = id >> 5;
            const int s4 = (id & 31) * 4;
            const int h = h0 + (col >> 6);
            const int d = col & 63;
            const float bv = vb[nb1023 + col];
            float v0 = Cs[(s4 + 0) * 132 + col] + bv;
            float v1 = Cs[(s4 + 1) * 132 + col] + bv;
            float v2 = Cs[(s4 + 2) * 132 + col] + bv;
            float v3 = Cs[(s4 + 3) * 132 + col] + bv;
            uint2 pk;
            pk.x = packh2(v0, v1);
            pk.y = packh2(v2, v3);
            *(uint2*)&g_VT[((size_t)(b * HH + h) * DD + d) * SS + s_base + s4] = pk;
        }
    }
}

// ---------------- HMMA banded flash attention (fp16) ------------------------
// SMEM: Qs 8KB @0, stage0 K 8KB @8192, V 8KB @16384, stage1 @24576/32768,
// fms 576 floats @40960. Total 43264 B.
#define ATT_SMEM 43264

__device__ __forceinline__ void att_issue(uint32_t sb, int stage, int t,
                                          int q0, int bh, int tid) {
    const int j0 = q0 - WW + t * 64;
    const uint32_t Kb = sb + 8192 + stage * 16384;
    const uint32_t Vb = Kb + 8192;
    const __half* Kg = g_Kb + (size_t)bh * SS * DD;
    const __half* Vg = g_VT + (size_t)bh * DD * SS;
#pragma unroll
    for (int i = 0; i < 4; i++) {
        const int u = tid + i * 128;
        const int r = u >> 3, p = u & 7;
        int jr = j0 + r;
        jr = (jr < 0) ? 0 : (jr > SS - 1 ? SS - 1 : jr);
        cp16(Kb + SWZ(r * 128 + p * 16), (const void*)(Kg + (size_t)jr * DD + p * 8));
        int jc = j0 + p * 8;
        jc = (jc < 0) ? 0 : (jc > SS - 8 ? SS - 8 : jc);
        cp16(Vb + SWZ(r * 128 + p * 16), (const void*)(Vg + (size_t)r * SS + jc));
    }
}

__global__ void __launch_bounds__(128) attn_hmma(const int* __restrict__ amask,
                                                 float* __restrict__ out) {
    extern __shared__ char smraw[];
    const uint32_t sb = smem_u32(smraw);
    float* fms = (float*)(smraw + 40960);

    const int tid = threadIdx.x;
    const int wid = tid >> 5;
    const int lane = tid & 31;
    const int qt = blockIdx.x & 63;
    const int h = (blockIdx.x >> 6) & 15;
    const int b = blockIdx.x >> 10;
    const int q0 = qt * 64;
    const int bh = b * HH + h;

    // Load Q tile (fp16, swizzled)
    {
        const __half* Qg = g_Qb + (size_t)(bh * SS + q0) * DD;
#pragma unroll
        for (int i = 0; i < 4; i++) {
            const int u = tid + i * 128;
            const int r = u >> 3, p = u & 7;
            uint4 v = *(const uint4*)(Qg + r * DD + p * 8);
            *(uint4*)(smraw + SWZ(r * 128 + p * 16)) = v;
        }
    }
    // fms for whole 576-key span
    for (int c = tid; c < 576; c += 128) {
        const int j = q0 - WW + c;
        fms[c] = (j >= 0 && j < SS && amask[b * SS + j] != 0) ? -10000.f : 0.f;
    }

    const int ks = (qt < 4) ? (4 - qt) : 0;
    const int ke = (qt > 59) ? (67 - qt) : 8;

    att_issue(sb, 0, ks, q0, bh, tid); CP_COMMIT();
    if (ks + 1 <= ke) att_issue(sb, 1, ks + 1, q0, bh, tid);
    CP_COMMIT();
    __syncthreads();

    // Q fragments (held for whole block)
    const int lrow = lane & 15;
    const int lsel = (lane >> 4) * 16;
    uint32_t qf[4][4];
#pragma unroll
    for (int kk = 0; kk < 4; kk++)
        ldsm4(qf[kk], sb + SWZ((wid * 16 + lrow) * 128 + kk * 32 + lsel));

    const int row0 = q0 + wid * 16 + (lane >> 2);
    const int row1 = row0 + 8;
    const int colb = (lane & 3) * 2;

    float m_[2] = {-1e30f, -1e30f};
    float l_[2] = {0.f, 0.f};
    float o[8][4];
#pragma unroll
    for (int dt = 0; dt < 8; dt++)
#pragma unroll
        for (int r = 0; r < 4; r++) o[dt][r] = 0.f;

    for (int t = ks; t <= ke; t++) {
        const int s = (t - ks) & 1;
        CP_WAIT1();
        __syncthreads();
        const int j0 = q0 - WW + t * 64;
        const uint32_t Kb = sb + 8192 + s * 16384;
        const uint32_t Vb = Kb + 8192;

        // ---- scores S = Q K^T ----
        float sf[8][4];
#pragma unroll
        for (int nt = 0; nt < 8; nt++)
#pragma unroll
            for (int r = 0; r < 4; r++) sf[nt][r] = 0.f;

#pragma unroll
        for (int kk = 0; kk < 4; kk++) {
            uint32_t bfr[4][4];
#pragma unroll
            for (int nn = 0; nn < 4; nn++)
                ldsm4(bfr[nn], Kb + SWZ((nn * 16 + lrow) * 128 + kk * 32 + lsel));
#pragma unroll
            for (int nt = 0; nt < 8; nt++)
                mma16816h(sf[nt], qf[kk],
                          bfr[nt >> 1][nt & 1], bfr[nt >> 1][(nt & 1) + 2]);
        }

        // ---- mask + online softmax ----
        float rm0 = -INFINITY, rm1 = -INFINITY;
#pragma unroll
        for (int nt = 0; nt < 8; nt++) {
#pragma unroll
            for (int e = 0; e < 2; e++) {
                const int kl = nt * 8 + colb + e;
                const int j = j0 + kl;
                const bool inr = (j >= 0) && (j < SS);
                const float fmv = fms[t * 64 + kl];
                const bool v0 = inr && (j - row0 <= WW) && (row0 - j <= WW);
                const bool v1 = inr && (j - row1 <= WW) && (row1 - j <= WW);
                sf[nt][e]     = v0 ? sf[nt][e] + fmv     : -INFINITY;
                sf[nt][2 + e] = v1 ? sf[nt][2 + e] + fmv : -INFINITY;
                rm0 = fmaxf(rm0, sf[nt][e]);
                rm1 = fmaxf(rm1, sf[nt][2 + e]);
            }
        }
        rm0 = fmaxf(rm0, __shfl_xor_sync(0xffffffffu, rm0, 1));
        rm0 = fmaxf(rm0, __shfl_xor_sync(0xffffffffu, rm0, 2));
        rm1 = fmaxf(rm1, __shfl_xor_sync(0xffffffffu, rm1, 1));
        rm1 = fmaxf(rm1, __shfl_xor_sync(0xffffffffu, rm1, 2));

        const float mn0 = fmaxf(m_[0], rm0);
        const float mn1 = fmaxf(m_[1], rm1);
        const float fs0 = __expf(m_[0] - mn0);
        const float fs1 = __expf(m_[1] - mn1);
        m_[0] = mn0; m_[1] = mn1;

        float rs0 = 0.f, rs1 = 0.f;
#pragma unroll
        for (int nt = 0; nt < 8; nt++) {
            sf[nt][0] = __expf(sf[nt][0] - mn0);
            sf[nt][1] = __expf(sf[nt][1] - mn0);
            sf[nt][2] = __expf(sf[nt][2] - mn1);
            sf[nt][3] = __expf(sf[nt][3] - mn1);
            rs0 += sf[nt][0] + sf[nt][1];
            rs1 += sf[nt][2] + sf[nt][3];
        }
        rs0 += __shfl_xor_sync(0xffffffffu, rs0, 1);
        rs0 += __shfl_xor_sync(0xffffffffu, rs0, 2);
        rs1 += __shfl_xor_sync(0xffffffffu, rs1, 1);
        rs1 += __shfl_xor_sync(0xffffffffu, rs1, 2);
        l_[0] = l_[0] * fs0 + rs0;
        l_[1] = l_[1] * fs1 + rs1;

#pragma unroll
        for (int dt = 0; dt < 8; dt++) {
            o[dt][0] *= fs0; o[dt][1] *= fs0;
            o[dt][2] *= fs1; o[dt][3] *= fs1;
        }

        // ---- P fragments (accumulator -> A-operand identity, fp16) ----
        uint32_t pf[4][4];
#pragma unroll
        for (int kc = 0; kc < 4; kc++) {
            pf[kc][0] = packh2(sf[2 * kc][0],     sf[2 * kc][1]);
            pf[kc][1] = packh2(sf[2 * kc][2],     sf[2 * kc][3]);
            pf[kc][2] = packh2(sf[2 * kc + 1][0], sf[2 * kc + 1][1]);
            pf[kc][3] = packh2(sf[2 * kc + 1][2], sf[2 * kc + 1][3]);
        }

        // ---- O += P V ----
#pragma unroll
        for (int kc = 0; kc < 4; kc++) {
            uint32_t vfr[4][4];
#pragma unroll
            for (int nn = 0; nn < 4; nn++)
                ldsm4(vfr[nn], Vb + SWZ((nn * 16 + lrow) * 128 + kc * 32 + lsel));
#pragma unroll
            for (int dt = 0; dt < 8; dt++)
                mma16816h(o[dt], pf[kc],
                          vfr[dt >> 1][dt & 1], vfr[dt >> 1][(dt & 1) + 2]);
        }

        __syncthreads();
        if (t + 2 <= ke) att_issue(sb, s, t + 2, q0, bh, tid);
        CP_COMMIT();
    }

    // ---- normalize + store ----
    const float inv0 = 1.f / l_[0];
    const float inv1 = 1.f / l_[1];
    const size_t base0 = ((size_t)b * SS + row0) * EE + h * 64;
    const size_t base1 = base0 + (size_t)8 * EE;
#pragma unroll
    for (int dt = 0; dt < 8; dt++) {
        const int d = dt * 8 + colb;
        float2 w0 = make_float2(o[dt][0] * inv0, o[dt][1] * inv0);
        float2 w1 = make_float2(o[dt][2] * inv1, o[dt][3] * inv1);
        *(float2*)&out[base0 + d] = w0;
        *(float2*)&out[base1 + d] = w1;
    }
}

// ---------------------------------------------------------------------------
extern "C" void kernel_launch(void* const* d_in, const int* in_sizes, int n_in,
                              void* d_out, int out_size) {
    const float* hs  = (const float*)d_in[0];
    const int*   am  = (const int*)d_in[1];
    const float* q_w = (const float*)d_in[2];
    const float* q_b = (const float*)d_in[3];
    const float* k_w = (const float*)d_in[4];
    const float* k_b = (const float*)d_in[5];
    const float* v_w = (const float*)d_in[6];
    const float* v_b = (const float*)d_in[7];
    float* out = (float*)d_out;

    cudaFuncSetAttribute(qkv_hmma_gemm, cudaFuncAttributeMaxDynamicSharedMemorySize,
                         GEMM_SMEM);
    cudaFuncSetAttribute(attn_hmma, cudaFuncAttributeMaxDynamicSharedMemorySize,
                         ATT_SMEM);

    split_x<<<(BB * SS * EE) / 1024, 256>>>(hs);
    split_w<<<(3 * EE * EE) / 1024, 256>>>(q_w, k_w, v_w);

    dim3 g(NTOT / NT, (BB * SS) / MT);   // (24, 64)
    qkv_hmma_gemm<<<g, 256, GEMM_SMEM>>>(q_b, k_b, v_b);

    attn_hmma<<<BB * HH * (SS / 64), 128, ATT_SMEM>>>(am, out);
}

// round 7
// speedup vs baseline: 6.9441x; 1.9732x over previous
#include <cuda_runtime.h>
#include <cuda_fp16.h>
#include <cstdint>
#include <math.h>

#define BB 2
#define SS 4096
#define EE 1024
#define HH 16
#define DD 64
#define WW 256

#define MT 128
#define NT 128
#define NTOT 3072
#define NCHUNK 16

typedef unsigned long long u64;

// ---------------- scratch (__device__ globals, no allocs) -------------------
__device__ __align__(16) __half g_Qb[BB * HH * SS * DD];  // [B,H,S,D] fp16
__device__ __align__(16) __half g_Kb[BB * HH * SS * DD];  // [B,H,S,D] fp16
__device__ __align__(16) __half g_VT[BB * HH * DD * SS];  // [B,H,D,S] fp16
__device__ __align__(16) __half g_Xf[BB * SS * EE];       // fp16 hidden states
__device__ __align__(16) __half g_Wf[NTOT * EE];          // fp16 Q|K|V weights

// ---------------- PTX helpers ----------------------------------------------
__device__ __forceinline__ uint32_t smem_u32(const void* p) {
    uint32_t a;
    asm("{ .reg .u64 t; cvta.to.shared.u64 t, %1; cvt.u32.u64 %0, t; }" : "=r"(a) : "l"(p));
    return a;
}
#define SWZ(o) ((o) ^ (((o) >> 3) & 0x70))

__device__ __forceinline__ void cp16(uint32_t s, const void* g) {
    asm volatile("cp.async.cg.shared.global [%0], [%1], 16;" :: "r"(s), "l"(g));
}
#define CP_COMMIT() asm volatile("cp.async.commit_group;" ::: "memory")
#define CP_WAIT1()  asm volatile("cp.async.wait_group 1;" ::: "memory")

__device__ __forceinline__ void ldsm4(uint32_t* r, uint32_t addr) {
    asm volatile("ldmatrix.sync.aligned.m8n8.x4.shared.b16 {%0,%1,%2,%3}, [%4];"
                 : "=r"(r[0]), "=r"(r[1]), "=r"(r[2]), "=r"(r[3]) : "r"(addr));
}
__device__ __forceinline__ void mma16816h(float* c, const uint32_t* a, uint32_t b0, uint32_t b1) {
    asm volatile("mma.sync.aligned.m16n8k16.row.col.f32.f16.f16.f32 "
                 "{%0,%1,%2,%3}, {%4,%5,%6,%7}, {%8,%9}, {%0,%1,%2,%3};"
                 : "+f"(c[0]), "+f"(c[1]), "+f"(c[2]), "+f"(c[3])
                 : "r"(a[0]), "r"(a[1]), "r"(a[2]), "r"(a[3]), "r"(b0), "r"(b1));
}
__device__ __forceinline__ uint32_t packh2(float lo, float hi) {
    uint32_t r;
    asm("cvt.rn.f16x2.f32 %0, %1, %2;" : "=r"(r) : "f"(hi), "f"(lo));
    return r;
}

// ---------------- fp32 -> fp16 convert kernels ------------------------------
__global__ void __launch_bounds__(256) conv_x(const float* __restrict__ X) {
    size_t i = ((size_t)blockIdx.x * 256 + threadIdx.x) * 4;
    float4 v = *(const float4*)(X + i);
    uint2 pk;
    pk.x = packh2(v.x, v.y);
    pk.y = packh2(v.z, v.w);
    *(uint2*)&g_Xf[i] = pk;
}

__global__ void __launch_bounds__(256) conv_w(const float* __restrict__ qw,
                                              const float* __restrict__ kw,
                                              const float* __restrict__ vw) {
    size_t i = ((size_t)blockIdx.x * 256 + threadIdx.x) * 4;
    int proj = (int)(i >> 20);
    const float* W = (proj == 0) ? qw : (proj == 1) ? kw : vw;
    size_t loc = i & ((1u << 20) - 1);
    float4 v = *(const float4*)(W + loc);
    uint2 pk;
    pk.x = packh2(v.x, v.y);
    pk.y = packh2(v.z, v.w);
    *(uint2*)&g_Wf[i] = pk;
}

// ---------------- HMMA QKV GEMM (fp16) --------------------------------------
#define GEMM_SMEM 67584

__device__ __forceinline__ void issue_loads(uint32_t sb, int stage, int chunk,
                                            int m0, int n0, int tid) {
    const int kc = chunk * 64;
    const uint32_t Ab = sb + stage * 32768;
    const uint32_t Bb = Ab + 16384;
#pragma unroll
    for (int i = 0; i < 4; i++) {
        int u = tid + i * 256;
        int r = u >> 3, p = u & 7;
        cp16(Ab + SWZ(r * 128 + p * 16), (const void*)(g_Xf + (size_t)(m0 + r) * EE + kc + p * 8));
        cp16(Bb + SWZ(r * 128 + p * 16), (const void*)(g_Wf + (size_t)(n0 + r) * EE + kc + p * 8));
    }
}

__global__ void __launch_bounds__(256) qkv_hmma_gemm(const float* __restrict__ qb,
                                                     const float* __restrict__ kb,
                                                     const float* __restrict__ vb) {
    extern __shared__ char smraw[];
    const uint32_t sb = smem_u32(smraw);
    const int tid = threadIdx.x;
    const int wid = tid >> 5;
    const int lane = tid & 31;
    const int n0 = blockIdx.x * NT;
    const int m0 = blockIdx.y * MT;

    const int warpRow = (wid & 1) * 64;
    const int warpCol = (wid >> 1) * 32;
    const int lrow = lane & 15;
    const int lsel = (lane >> 4) * 16;

    float acc[4][4][4];
#pragma unroll
    for (int mi = 0; mi < 4; mi++)
#pragma unroll
        for (int ni = 0; ni < 4; ni++)
#pragma unroll
            for (int r = 0; r < 4; r++) acc[mi][ni][r] = 0.f;

    issue_loads(sb, 0, 0, m0, n0, tid); CP_COMMIT();
    issue_loads(sb, 1, 1, m0, n0, tid); CP_COMMIT();

    for (int c = 0; c < NCHUNK; c++) {
        const int s = c & 1;
        CP_WAIT1();
        __syncthreads();
        const uint32_t Ab = sb + s * 32768;
        const uint32_t Bb = Ab + 16384;
#pragma unroll
        for (int kk = 0; kk < 4; kk++) {
            uint32_t afr[4][4];
#pragma unroll
            for (int mi = 0; mi < 4; mi++) {
                uint32_t o = (warpRow + mi * 16 + lrow) * 128 + kk * 32 + lsel;
                ldsm4(afr[mi], Ab + SWZ(o));
            }
            uint32_t bfr[2][4];
#pragma unroll
            for (int bi = 0; bi < 2; bi++) {
                uint32_t o = (warpCol + bi * 16 + lrow) * 128 + kk * 32 + lsel;
                ldsm4(bfr[bi], Bb + SWZ(o));
            }
#pragma unroll
            for (int mi = 0; mi < 4; mi++)
#pragma unroll
                for (int ni = 0; ni < 4; ni++)
                    mma16816h(acc[mi][ni], afr[mi],
                              bfr[ni >> 1][ni & 1], bfr[ni >> 1][(ni & 1) + 2]);
        }
        __syncthreads();
        if (c + 2 < NCHUNK) issue_loads(sb, s, c + 2, m0, n0, tid);
        CP_COMMIT();
    }
    __syncthreads();

    // -------- epilogue: stage C in smem, bias + fp16 + layout transform -----
    float* Cs = (float*)smraw;   // [128][132]
#pragma unroll
    for (int mi = 0; mi < 4; mi++)
#pragma unroll
        for (int ni = 0; ni < 4; ni++) {
            const int r = warpRow + mi * 16 + (lane >> 2);
            const int col = warpCol + ni * 8 + (lane & 3) * 2;
            Cs[r * 132 + col]       = acc[mi][ni][0];
            Cs[r * 132 + col + 1]   = acc[mi][ni][1];
            Cs[(r + 8) * 132 + col]     = acc[mi][ni][2];
            Cs[(r + 8) * 132 + col + 1] = acc[mi][ni][3];
        }
    __syncthreads();

    const int proj = n0 >> 10;
    const int nb1023 = n0 & 1023;
    const int h0 = nb1023 >> 6;
    const int b = m0 >> 12;
    const int s_base = m0 & (SS - 1);

    if (proj < 2) {
        __half* dst = (proj == 0) ? g_Qb : g_Kb;
        const float* bp = (proj == 0) ? qb : kb;
        const float scale = (proj == 0) ? 0.125f : 1.0f;
#pragma unroll
        for (int it = 0; it < 16; it++) {
            const int id = tid + it * 256;
            const int col = (id & 31) * 4;
            const int s = id >> 5;
            const int h = h0 + (col >> 6);
            const int d = col & 63;
            float v0 = (Cs[s * 132 + col]     + bp[nb1023 + col])     * scale;
            float v1 = (Cs[s * 132 + col + 1] + bp[nb1023 + col + 1]) * scale;
            float v2 = (Cs[s * 132 + col + 2] + bp[nb1023 + col + 2]) * scale;
            float v3 = (Cs[s * 132 + col + 3] + bp[nb1023 + col + 3]) * scale;
            uint2 pk;
            pk.x = packh2(v0, v1);
            pk.y = packh2(v2, v3);
            *(uint2*)&dst[((size_t)(b * HH + h) * SS + s_base + s) * DD + d] = pk;
        }
    } else {
#pragma unroll
        for (int it = 0; it < 16; it++) {
            const int id = tid + it * 256;
            const int col = id >> 5;
            const int s4 = (id & 31) * 4;
            const int h = h0 + (col >> 6);
            const int d = col & 63;
            const float bv = vb[nb1023 + col];
            float v0 = Cs[(s4 + 0) * 132 + col] + bv;
            float v1 = Cs[(s4 + 1) * 132 + col] + bv;
            float v2 = Cs[(s4 + 2) * 132 + col] + bv;
            float v3 = Cs[(s4 + 3) * 132 + col] + bv;
            uint2 pk;
            pk.x = packh2(v0, v1);
            pk.y = packh2(v2, v3);
            *(uint2*)&g_VT[((size_t)(b * HH + h) * DD + d) * SS + s_base + s4] = pk;
        }
    }
}

// ---------------- HMMA banded flash attention (fp16) ------------------------
// SMEM: Qs 8KB @0, stage0 K 8KB @8192, V 8KB @16384, stage1 @24576/32768,
// fms 576 floats @40960. Total 43264 B.
#define ATT_SMEM 43264

__device__ __forceinline__ void att_issue(uint32_t sb, int stage, int t,
                                          int q0, int bh, int tid) {
    const int j0 = q0 - WW + t * 64;
    const uint32_t Kb = sb + 8192 + stage * 16384;
    const uint32_t Vb = Kb + 8192;
    const __half* Kg = g_Kb + (size_t)bh * SS * DD;
    const __half* Vg = g_VT + (size_t)bh * DD * SS;
#pragma unroll
    for (int i = 0; i < 4; i++) {
        const int u = tid + i * 128;
        const int r = u >> 3, p = u & 7;
        int jr = j0 + r;
        jr = (jr < 0) ? 0 : (jr > SS - 1 ? SS - 1 : jr);
        cp16(Kb + SWZ(r * 128 + p * 16), (const void*)(Kg + (size_t)jr * DD + p * 8));
        int jc = j0 + p * 8;
        jc = (jc < 0) ? 0 : (jc > SS - 8 ? SS - 8 : jc);
        cp16(Vb + SWZ(r * 128 + p * 16), (const void*)(Vg + (size_t)r * SS + jc));
    }
}

__global__ void __launch_bounds__(128) attn_hmma(const int* __restrict__ amask,
                                                 float* __restrict__ out) {
    extern __shared__ char smraw[];
    const uint32_t sb = smem_u32(smraw);
    float* fms = (float*)(smraw + 40960);

    const int tid = threadIdx.x;
    const int wid = tid >> 5;
    const int lane = tid & 31;
    const int qt = blockIdx.x & 63;
    const int h = (blockIdx.x >> 6) & 15;
    const int b = blockIdx.x >> 10;
    const int q0 = qt * 64;
    const int bh = b * HH + h;

    // Load Q tile (fp16, swizzled)
    {
        const __half* Qg = g_Qb + (size_t)(bh * SS + q0) * DD;
#pragma unroll
        for (int i = 0; i < 4; i++) {
            const int u = tid + i * 128;
            const int r = u >> 3, p = u & 7;
            uint4 v = *(const uint4*)(Qg + r * DD + p * 8);
            *(uint4*)(smraw + SWZ(r * 128 + p * 16)) = v;
        }
    }
    // fms for whole 576-key span
    for (int c = tid; c < 576; c += 128) {
        const int j = q0 - WW + c;
        fms[c] = (j >= 0 && j < SS && amask[b * SS + j] != 0) ? -10000.f : 0.f;
    }

    const int ks = (qt < 4) ? (4 - qt) : 0;
    const int ke = (qt > 59) ? (67 - qt) : 8;

    att_issue(sb, 0, ks, q0, bh, tid); CP_COMMIT();
    if (ks + 1 <= ke) att_issue(sb, 1, ks + 1, q0, bh, tid);
    CP_COMMIT();
    __syncthreads();

    // Q fragments (held for whole block)
    const int lrow = lane & 15;
    const int lsel = (lane >> 4) * 16;
    uint32_t qf[4][4];
#pragma unroll
    for (int kk = 0; kk < 4; kk++)
        ldsm4(qf[kk], sb + SWZ((wid * 16 + lrow) * 128 + kk * 32 + lsel));

    const int row0 = q0 + wid * 16 + (lane >> 2);
    const int row1 = row0 + 8;
    const int colb = (lane & 3) * 2;

    float m_[2] = {-1e30f, -1e30f};
    float l_[2] = {0.f, 0.f};
    float o[8][4];
#pragma unroll
    for (int dt = 0; dt < 8; dt++)
#pragma unroll
        for (int r = 0; r < 4; r++) o[dt][r] = 0.f;

    for (int t = ks; t <= ke; t++) {
        const int s = (t - ks) & 1;
        CP_WAIT1();
        __syncthreads();
        const int j0 = q0 - WW + t * 64;
        const uint32_t Kb = sb + 8192 + s * 16384;
        const uint32_t Vb = Kb + 8192;

        // ---- scores S = Q K^T ----
        float sf[8][4];
#pragma unroll
        for (int nt = 0; nt < 8; nt++)
#pragma unroll
            for (int r = 0; r < 4; r++) sf[nt][r] = 0.f;

#pragma unroll
        for (int kk = 0; kk < 4; kk++) {
            uint32_t bfr[4][4];
#pragma unroll
            for (int nn = 0; nn < 4; nn++)
                ldsm4(bfr[nn], Kb + SWZ((nn * 16 + lrow) * 128 + kk * 32 + lsel));
#pragma unroll
            for (int nt = 0; nt < 8; nt++)
                mma16816h(sf[nt], qf[kk],
                          bfr[nt >> 1][nt & 1], bfr[nt >> 1][(nt & 1) + 2]);
        }

        // ---- mask + online softmax ----
        float rm0 = -INFINITY, rm1 = -INFINITY;
#pragma unroll
        for (int nt = 0; nt < 8; nt++) {
#pragma unroll
            for (int e = 0; e < 2; e++) {
                const int kl = nt * 8 + colb + e;
                const int j = j0 + kl;
                const bool inr = (j >= 0) && (j < SS);
                const float fmv = fms[t * 64 + kl];
                const bool v0 = inr && (j - row0 <= WW) && (row0 - j <= WW);
                const bool v1 = inr && (j - row1 <= WW) && (row1 - j <= WW);
                sf[nt][e]     = v0 ? sf[nt][e] + fmv     : -INFINITY;
                sf[nt][2 + e] = v1 ? sf[nt][2 + e] + fmv : -INFINITY;
                rm0 = fmaxf(rm0, sf[nt][e]);
                rm1 = fmaxf(rm1, sf[nt][2 + e]);
            }
        }
        rm0 = fmaxf(rm0, __shfl_xor_sync(0xffffffffu, rm0, 1));
        rm0 = fmaxf(rm0, __shfl_xor_sync(0xffffffffu, rm0, 2));
        rm1 = fmaxf(rm1, __shfl_xor_sync(0xffffffffu, rm1, 1));
        rm1 = fmaxf(rm1, __shfl_xor_sync(0xffffffffu, rm1, 2));

        const float mn0 = fmaxf(m_[0], rm0);
        const float mn1 = fmaxf(m_[1], rm1);
        const float fs0 = __expf(m_[0] - mn0);
        const float fs1 = __expf(m_[1] - mn1);
        m_[0] = mn0; m_[1] = mn1;

        float rs0 = 0.f, rs1 = 0.f;
#pragma unroll
        for (int nt = 0; nt < 8; nt++) {
            sf[nt][0] = __expf(sf[nt][0] - mn0);
            sf[nt][1] = __expf(sf[nt][1] - mn0);
            sf[nt][2] = __expf(sf[nt][2] - mn1);
            sf[nt][3] = __expf(sf[nt][3] - mn1);
            rs0 += sf[nt][0] + sf[nt][1];
            rs1 += sf[nt][2] + sf[nt][3];
        }
        rs0 += __shfl_xor_sync(0xffffffffu, rs0, 1);
        rs0 += __shfl_xor_sync(0xffffffffu, rs0, 2);
        rs1 += __shfl_xor_sync(0xffffffffu, rs1, 1);
        rs1 += __shfl_xor_sync(0xffffffffu, rs1, 2);
        l_[0] = l_[0] * fs0 + rs0;
        l_[1] = l_[1] * fs1 + rs1;

#pragma unroll
        for (int dt = 0; dt < 8; dt++) {
            o[dt][0] *= fs0; o[dt][1] *= fs0;
            o[dt][2] *= fs1; o[dt][3] *= fs1;
        }

        // ---- P fragments (accumulator -> A-operand identity, fp16) ----
        uint32_t pf[4][4];
#pragma unroll
        for (int kc = 0; kc < 4; kc++) {
            pf[kc][0] = packh2(sf[2 * kc][0],     sf[2 * kc][1]);
            pf[kc][1] = packh2(sf[2 * kc][2],     sf[2 * kc][3]);
            pf[kc][2] = packh2(sf[2 * kc + 1][0], sf[2 * kc + 1][1]);
            pf[kc][3] = packh2(sf[2 * kc + 1][2], sf[2 * kc + 1][3]);
        }

        // ---- O += P V ----
#pragma unroll
        for (int kc = 0; kc < 4; kc++) {
            uint32_t vfr[4][4];
#pragma unroll
            for (int nn = 0; nn < 4; nn++)
                ldsm4(vfr[nn], Vb + SWZ((nn * 16 + lrow) * 128 + kc * 32 + lsel));
#pragma unroll
            for (int dt = 0; dt < 8; dt++)
                mma16816h(o[dt], pf[kc],
                          vfr[dt >> 1][dt & 1], vfr[dt >> 1][(dt & 1) + 2]);
        }

        __syncthreads();
        if (t + 2 <= ke) att_issue(sb, s, t + 2, q0, bh, tid);
        CP_COMMIT();
    }

    // ---- normalize + store ----
    const float inv0 = 1.f / l_[0];
    const float inv1 = 1.f / l_[1];
    const size_t base0 = ((size_t)b * SS + row0) * EE + h * 64;
    const size_t base1 = base0 + (size_t)8 * EE;
#pragma unroll
    for (int dt = 0; dt < 8; dt++) {
        const int d = dt * 8 + colb;
        float2 w0 = make_float2(o[dt][0] * inv0, o[dt][1] * inv0);
        float2 w1 = make_float2(o[dt][2] * inv1, o[dt][3] * inv1);
        *(float2*)&out[base0 + d] = w0;
        *(float2*)&out[base1 + d] = w1;
    }
}

// ---------------------------------------------------------------------------
extern "C" void kernel_launch(void* const* d_in, const int* in_sizes, int n_in,
                              void* d_out, int out_size) {
    const float* hs  = (const float*)d_in[0];
    const int*   am  = (const int*)d_in[1];
    const float* q_w = (const float*)d_in[2];
    const float* q_b = (const float*)d_in[3];
    const float* k_w = (const float*)d_in[4];
    const float* k_b = (const float*)d_in[5];
    const float* v_w = (const float*)d_in[6];
    const float* v_b = (const float*)d_in[7];
    float* out = (float*)d_out;

    cudaFuncSetAttribute(qkv_hmma_gemm, cudaFuncAttributeMaxDynamicSharedMemorySize,
                         GEMM_SMEM);
    cudaFuncSetAttribute(attn_hmma, cudaFuncAttributeMaxDynamicSharedMemorySize,
                         ATT_SMEM);

    conv_x<<<(BB * SS * EE) / 1024, 256>>>(hs);
    conv_w<<<(3 * EE * EE) / 1024, 256>>>(q_w, k_w, v_w);

    dim3 g(NTOT / NT, (BB * SS) / MT);   // (24, 64)
    qkv_hmma_gemm<<<g, 256, GEMM_SMEM>>>(q_b, k_b, v_b);

    attn_hmma<<<BB * HH * (SS / 64), 128, ATT_SMEM>>>(am, out);
}

// round 8
// speedup vs baseline: 7.5350x; 1.0851x over previous
#include <cuda_runtime.h>
#include <cuda_fp16.h>
#include <cstdint>
#include <math.h>

#define BB 2
#define SS 4096
#define EE 1024
#define HH 16
#define DD 64
#define WW 256

#define MT 128
#define NT 128
#define NTOT 3072
#define NCHUNK 16

typedef unsigned long long u64;

// ---------------- scratch (__device__ globals, no allocs) -------------------
__device__ __align__(16) __half g_Qb[BB * HH * SS * DD];  // [B,H,S,D] fp16
__device__ __align__(16) __half g_Kb[BB * HH * SS * DD];  // [B,H,S,D] fp16
__device__ __align__(16) __half g_VT[BB * HH * DD * SS];  // [B,H,D,S] fp16
__device__ __align__(16) __half g_Xf[BB * SS * EE];       // fp16 hidden states
__device__ __align__(16) __half g_Wf[NTOT * EE];          // fp16 Q|K|V weights

// ---------------- PTX helpers ----------------------------------------------
__device__ __forceinline__ uint32_t smem_u32(const void* p) {
    uint32_t a;
    asm("{ .reg .u64 t; cvta.to.shared.u64 t, %1; cvt.u32.u64 %0, t; }" : "=r"(a) : "l"(p));
    return a;
}
#define SWZ(o) ((o) ^ (((o) >> 3) & 0x70))

__device__ __forceinline__ void cp16(uint32_t s, const void* g) {
    asm volatile("cp.async.cg.shared.global [%0], [%1], 16;" :: "r"(s), "l"(g));
}
#define CP_COMMIT() asm volatile("cp.async.commit_group;" ::: "memory")
#define CP_WAIT1()  asm volatile("cp.async.wait_group 1;" ::: "memory")
#define CP_WAIT2()  asm volatile("cp.async.wait_group 2;" ::: "memory")

__device__ __forceinline__ void ldsm4(uint32_t* r, uint32_t addr) {
    asm volatile("ldmatrix.sync.aligned.m8n8.x4.shared.b16 {%0,%1,%2,%3}, [%4];"
                 : "=r"(r[0]), "=r"(r[1]), "=r"(r[2]), "=r"(r[3]) : "r"(addr));
}
__device__ __forceinline__ void mma16816h(float* c, const uint32_t* a, uint32_t b0, uint32_t b1) {
    asm volatile("mma.sync.aligned.m16n8k16.row.col.f32.f16.f16.f32 "
                 "{%0,%1,%2,%3}, {%4,%5,%6,%7}, {%8,%9}, {%0,%1,%2,%3};"
                 : "+f"(c[0]), "+f"(c[1]), "+f"(c[2]), "+f"(c[3])
                 : "r"(a[0]), "r"(a[1]), "r"(a[2]), "r"(a[3]), "r"(b0), "r"(b1));
}
__device__ __forceinline__ uint32_t packh2(float lo, float hi) {
    uint32_t r;
    asm("cvt.rn.f16x2.f32 %0, %1, %2;" : "=r"(r) : "f"(hi), "f"(lo));
    return r;
}

// ---------------- fp32 -> fp16 convert kernels ------------------------------
__global__ void __launch_bounds__(256) conv_x(const float* __restrict__ X) {
    size_t i = ((size_t)blockIdx.x * 256 + threadIdx.x) * 4;
    float4 v = *(const float4*)(X + i);
    uint2 pk;
    pk.x = packh2(v.x, v.y);
    pk.y = packh2(v.z, v.w);
    *(uint2*)&g_Xf[i] = pk;
}

__global__ void __launch_bounds__(256) conv_w(const float* __restrict__ qw,
                                              const float* __restrict__ kw,
                                              const float* __restrict__ vw) {
    size_t i = ((size_t)blockIdx.x * 256 + threadIdx.x) * 4;
    int proj = (int)(i >> 20);
    const float* W = (proj == 0) ? qw : (proj == 1) ? kw : vw;
    size_t loc = i & ((1u << 20) - 1);
    float4 v = *(const float4*)(W + loc);
    uint2 pk;
    pk.x = packh2(v.x, v.y);
    pk.y = packh2(v.z, v.w);
    *(uint2*)&g_Wf[i] = pk;
}

// ---------------- HMMA QKV GEMM (fp16, 3-stage pipeline) --------------------
#define GEMM_SMEM 98304

__device__ __forceinline__ void issue_loads(uint32_t sb, int stage, int chunk,
                                            int m0, int n0, int tid) {
    const int kc = chunk * 64;
    const uint32_t Ab = sb + stage * 32768;
    const uint32_t Bb = Ab + 16384;
#pragma unroll
    for (int i = 0; i < 4; i++) {
        int u = tid + i * 256;
        int r = u >> 3, p = u & 7;
        cp16(Ab + SWZ(r * 128 + p * 16), (const void*)(g_Xf + (size_t)(m0 + r) * EE + kc + p * 8));
        cp16(Bb + SWZ(r * 128 + p * 16), (const void*)(g_Wf + (size_t)(n0 + r) * EE + kc + p * 8));
    }
}

__global__ void __launch_bounds__(256) qkv_hmma_gemm(const float* __restrict__ qb,
                                                     const float* __restrict__ kb,
                                                     const float* __restrict__ vb) {
    extern __shared__ char smraw[];
    const uint32_t sb = smem_u32(smraw);
    const int tid = threadIdx.x;
    const int wid = tid >> 5;
    const int lane = tid & 31;
    const int n0 = blockIdx.x * NT;
    const int m0 = blockIdx.y * MT;

    const int warpRow = (wid & 1) * 64;
    const int warpCol = (wid >> 1) * 32;
    const int lrow = lane & 15;
    const int lsel = (lane >> 4) * 16;

    float acc[4][4][4];
#pragma unroll
    for (int mi = 0; mi < 4; mi++)
#pragma unroll
        for (int ni = 0; ni < 4; ni++)
#pragma unroll
            for (int r = 0; r < 4; r++) acc[mi][ni][r] = 0.f;

    issue_loads(sb, 0, 0, m0, n0, tid); CP_COMMIT();
    issue_loads(sb, 1, 1, m0, n0, tid); CP_COMMIT();
    issue_loads(sb, 2, 2, m0, n0, tid); CP_COMMIT();

    int stage = 0;
    for (int c = 0; c < NCHUNK; c++) {
        CP_WAIT2();
        __syncthreads();
        const uint32_t Ab = sb + stage * 32768;
        const uint32_t Bb = Ab + 16384;
#pragma unroll
        for (int kk = 0; kk < 4; kk++) {
            uint32_t afr[4][4];
#pragma unroll
            for (int mi = 0; mi < 4; mi++) {
                uint32_t o = (warpRow + mi * 16 + lrow) * 128 + kk * 32 + lsel;
                ldsm4(afr[mi], Ab + SWZ(o));
            }
            uint32_t bfr[2][4];
#pragma unroll
            for (int bi = 0; bi < 2; bi++) {
                uint32_t o = (warpCol + bi * 16 + lrow) * 128 + kk * 32 + lsel;
                ldsm4(bfr[bi], Bb + SWZ(o));
            }
#pragma unroll
            for (int mi = 0; mi < 4; mi++)
#pragma unroll
                for (int ni = 0; ni < 4; ni++)
                    mma16816h(acc[mi][ni], afr[mi],
                              bfr[ni >> 1][ni & 1], bfr[ni >> 1][(ni & 1) + 2]);
        }
        __syncthreads();
        if (c + 3 < NCHUNK) issue_loads(sb, stage, c + 3, m0, n0, tid);
        CP_COMMIT();
        stage = (stage == 2) ? 0 : stage + 1;
    }
    __syncthreads();

    // -------- epilogue: stage C in smem, bias + fp16 + layout transform -----
    float* Cs = (float*)smraw;   // [128][132]
#pragma unroll
    for (int mi = 0; mi < 4; mi++)
#pragma unroll
        for (int ni = 0; ni < 4; ni++) {
            const int r = warpRow + mi * 16 + (lane >> 2);
            const int col = warpCol + ni * 8 + (lane & 3) * 2;
            Cs[r * 132 + col]       = acc[mi][ni][0];
            Cs[r * 132 + col + 1]   = acc[mi][ni][1];
            Cs[(r + 8) * 132 + col]     = acc[mi][ni][2];
            Cs[(r + 8) * 132 + col + 1] = acc[mi][ni][3];
        }
    __syncthreads();

    const int proj = n0 >> 10;
    const int nb1023 = n0 & 1023;
    const int h0 = nb1023 >> 6;
    const int b = m0 >> 12;
    const int s_base = m0 & (SS - 1);

    if (proj < 2) {
        __half* dst = (proj == 0) ? g_Qb : g_Kb;
        const float* bp = (proj == 0) ? qb : kb;
        const float scale = (proj == 0) ? 0.125f : 1.0f;
#pragma unroll
        for (int it = 0; it < 16; it++) {
            const int id = tid + it * 256;
            const int col = (id & 31) * 4;
            const int s = id >> 5;
            const int h = h0 + (col >> 6);
            const int d = col & 63;
            float v0 = (Cs[s * 132 + col]     + bp[nb1023 + col])     * scale;
            float v1 = (Cs[s * 132 + col + 1] + bp[nb1023 + col + 1]) * scale;
            float v2 = (Cs[s * 132 + col + 2] + bp[nb1023 + col + 2]) * scale;
            float v3 = (Cs[s * 132 + col + 3] + bp[nb1023 + col + 3]) * scale;
            uint2 pk;
            pk.x = packh2(v0, v1);
            pk.y = packh2(v2, v3);
            *(uint2*)&dst[((size_t)(b * HH + h) * SS + s_base + s) * DD + d] = pk;
        }
    } else {
#pragma unroll
        for (int it = 0; it < 16; it++) {
            const int id = tid + it * 256;
            const int col = id >> 5;
            const int s4 = (id & 31) * 4;
            const int h = h0 + (col >> 6);
            const int d = col & 63;
            const float bv = vb[nb1023 + col];
            float v0 = Cs[(s4 + 0) * 132 + col] + bv;
            float v1 = Cs[(s4 + 1) * 132 + col] + bv;
            float v2 = Cs[(s4 + 2) * 132 + col] + bv;
            float v3 = Cs[(s4 + 3) * 132 + col] + bv;
            uint2 pk;
            pk.x = packh2(v0, v1);
            pk.y = packh2(v2, v3);
            *(uint2*)&g_VT[((size_t)(b * HH + h) * DD + d) * SS + s_base + s4] = pk;
        }
    }
}

// ---------------- HMMA banded flash attention (fp16) ------------------------
// SMEM: Qs 8KB @0, stage0 K 8KB @8192, V 8KB @16384, stage1 @24576/32768,
// fms 576 floats @40960. Total 43264 B.
#define ATT_SMEM 43264

__device__ __forceinline__ void att_issue(uint32_t sb, int stage, int t,
                                          int q0, int bh, int tid) {
    const int j0 = q0 - WW + t * 64;   // always in [0, SS-64] given ks/ke
    const uint32_t Kb = sb + 8192 + stage * 16384;
    const uint32_t Vb = Kb + 8192;
    const __half* Kg = g_Kb + (size_t)bh * SS * DD + (size_t)j0 * DD;
    const __half* Vg = g_VT + (size_t)bh * DD * SS + j0;
#pragma unroll
    for (int i = 0; i < 4; i++) {
        const int u = tid + i * 128;
        const int r = u >> 3, p = u & 7;
        cp16(Kb + SWZ(r * 128 + p * 16), (const void*)(Kg + (size_t)r * DD + p * 8));
        cp16(Vb + SWZ(r * 128 + p * 16), (const void*)(Vg + (size_t)r * SS + p * 8));
    }
}

__global__ void __launch_bounds__(128) attn_hmma(const int* __restrict__ amask,
                                                 float* __restrict__ out) {
    extern __shared__ char smraw[];
    const uint32_t sb = smem_u32(smraw);
    float* fms = (float*)(smraw + 40960);

    const int tid = threadIdx.x;
    const int wid = tid >> 5;
    const int lane = tid & 31;
    const int qt = blockIdx.x & 63;
    const int h = (blockIdx.x >> 6) & 15;
    const int b = blockIdx.x >> 10;
    const int q0 = qt * 64;
    const int bh = b * HH + h;

    // Load Q tile (fp16, swizzled)
    {
        const __half* Qg = g_Qb + (size_t)(bh * SS + q0) * DD;
#pragma unroll
        for (int i = 0; i < 4; i++) {
            const int u = tid + i * 128;
            const int r = u >> 3, p = u & 7;
            uint4 v = *(const uint4*)(Qg + r * DD + p * 8);
            *(uint4*)(smraw + SWZ(r * 128 + p * 16)) = v;
        }
    }
    // fms for whole 576-key span
    for (int c = tid; c < 576; c += 128) {
        const int j = q0 - WW + c;
        fms[c] = (j >= 0 && j < SS && amask[b * SS + j] != 0) ? -10000.f : 0.f;
    }

    const int ks = (qt < 4) ? (4 - qt) : 0;
    const int ke = (qt > 59) ? (67 - qt) : 8;

    att_issue(sb, 0, ks, q0, bh, tid); CP_COMMIT();
    if (ks + 1 <= ke) att_issue(sb, 1, ks + 1, q0, bh, tid);
    CP_COMMIT();
    __syncthreads();

    // Q fragments (held for whole block)
    const int lrow = lane & 15;
    const int lsel = (lane >> 4) * 16;
    uint32_t qf[4][4];
#pragma unroll
    for (int kk = 0; kk < 4; kk++)
        ldsm4(qf[kk], sb + SWZ((wid * 16 + lrow) * 128 + kk * 32 + lsel));

    const int row0 = q0 + wid * 16 + (lane >> 2);
    const int row1 = row0 + 8;
    const int colb = (lane & 3) * 2;

    float m_[2] = {-1e30f, -1e30f};
    float l_[2] = {0.f, 0.f};
    float o[8][4];
#pragma unroll
    for (int dt = 0; dt < 8; dt++)
#pragma unroll
        for (int r = 0; r < 4; r++) o[dt][r] = 0.f;

    for (int t = ks; t <= ke; t++) {
        const int s = (t - ks) & 1;
        CP_WAIT1();
        __syncthreads();
        const int j0 = q0 - WW + t * 64;
        const uint32_t Kb = sb + 8192 + s * 16384;
        const uint32_t Vb = Kb + 8192;

        // ---- scores S = Q K^T ----
        float sf[8][4];
#pragma unroll
        for (int nt = 0; nt < 8; nt++)
#pragma unroll
            for (int r = 0; r < 4; r++) sf[nt][r] = 0.f;

#pragma unroll
        for (int kk = 0; kk < 4; kk++) {
            uint32_t bfr[4][4];
#pragma unroll
            for (int nn = 0; nn < 4; nn++)
                ldsm4(bfr[nn], Kb + SWZ((nn * 16 + lrow) * 128 + kk * 32 + lsel));
#pragma unroll
            for (int nt = 0; nt < 8; nt++)
                mma16816h(sf[nt], qf[kk],
                          bfr[nt >> 1][nt & 1], bfr[nt >> 1][(nt & 1) + 2]);
        }

        // ---- mask + online softmax ----
        // All loaded tiles lie fully within [0,SS). Band |j-i|<=W can only be
        // violated in tiles t==0 (left edge) and t==8 (right edge).
        float rm0 = -INFINITY, rm1 = -INFINITY;
        if (t == 0 || t == 8) {
#pragma unroll
            for (int nt = 0; nt < 8; nt++) {
#pragma unroll
                for (int e = 0; e < 2; e++) {
                    const int kl = nt * 8 + colb + e;
                    const int j = j0 + kl;
                    const float fmv = fms[t * 64 + kl];
                    const bool v0 = (j - row0 <= WW) && (row0 - j <= WW);
                    const bool v1 = (j - row1 <= WW) && (row1 - j <= WW);
                    sf[nt][e]     = v0 ? sf[nt][e] + fmv     : -INFINITY;
                    sf[nt][2 + e] = v1 ? sf[nt][2 + e] + fmv : -INFINITY;
                    rm0 = fmaxf(rm0, sf[nt][e]);
                    rm1 = fmaxf(rm1, sf[nt][2 + e]);
                }
            }
        } else {
#pragma unroll
            for (int nt = 0; nt < 8; nt++) {
                const float fmv0 = fms[t * 64 + nt * 8 + colb];
                const float fmv1 = fms[t * 64 + nt * 8 + colb + 1];
                sf[nt][0] += fmv0; sf[nt][1] += fmv1;
                sf[nt][2] += fmv0; sf[nt][3] += fmv1;
                rm0 = fmaxf(rm0, fmaxf(sf[nt][0], sf[nt][1]));
                rm1 = fmaxf(rm1, fmaxf(sf[nt][2], sf[nt][3]));
            }
        }
        rm0 = fmaxf(rm0, __shfl_xor_sync(0xffffffffu, rm0, 1));
        rm0 = fmaxf(rm0, __shfl_xor_sync(0xffffffffu, rm0, 2));
        rm1 = fmaxf(rm1, __shfl_xor_sync(0xffffffffu, rm1, 1));
        rm1 = fmaxf(rm1, __shfl_xor_sync(0xffffffffu, rm1, 2));

        const float mn0 = fmaxf(m_[0], rm0);
        const float mn1 = fmaxf(m_[1], rm1);
        const float fs0 = __expf(m_[0] - mn0);
        const float fs1 = __expf(m_[1] - mn1);
        m_[0] = mn0; m_[1] = mn1;

        float rs0 = 0.f, rs1 = 0.f;
#pragma unroll
        for (int nt = 0; nt < 8; nt++) {
            sf[nt][0] = __expf(sf[nt][0] - mn0);
            sf[nt][1] = __expf(sf[nt][1] - mn0);
            sf[nt][2] = __expf(sf[nt][2] - mn1);
            sf[nt][3] = __expf(sf[nt][3] - mn1);
            rs0 += sf[nt][0] + sf[nt][1];
            rs1 += sf[nt][2] + sf[nt][3];
        }
        rs0 += __shfl_xor_sync(0xffffffffu, rs0, 1);
        rs0 += __shfl_xor_sync(0xffffffffu, rs0, 2);
        rs1 += __shfl_xor_sync(0xffffffffu, rs1, 1);
        rs1 += __shfl_xor_sync(0xffffffffu, rs1, 2);
        l_[0] = l_[0] * fs0 + rs0;
        l_[1] = l_[1] * fs1 + rs1;

#pragma unroll
        for (int dt = 0; dt < 8; dt++) {
            o[dt][0] *= fs0; o[dt][1] *= fs0;
            o[dt][2] *= fs1; o[dt][3] *= fs1;
        }

        // ---- P fragments (accumulator -> A-operand identity, fp16) ----
        uint32_t pf[4][4];
#pragma unroll
        for (int kc = 0; kc < 4; kc++) {
            pf[kc][0] = packh2(sf[2 * kc][0],     sf[2 * kc][1]);
            pf[kc][1] = packh2(sf[2 * kc][2],     sf[2 * kc][3]);
            pf[kc][2] = packh2(sf[2 * kc + 1][0], sf[2 * kc + 1][1]);
            pf[kc][3] = packh2(sf[2 * kc + 1][2], sf[2 * kc + 1][3]);
        }

        // ---- O += P V ----
#pragma unroll
        for (int kc = 0; kc < 4; kc++) {
            uint32_t vfr[4][4];
#pragma unroll
            for (int nn = 0; nn < 4; nn++)
                ldsm4(vfr[nn], Vb + SWZ((nn * 16 + lrow) * 128 + kc * 32 + lsel));
#pragma unroll
            for (int dt = 0; dt < 8; dt++)
                mma16816h(o[dt], pf[kc],
                          vfr[dt >> 1][dt & 1], vfr[dt >> 1][(dt & 1) + 2]);
        }

        __syncthreads();
        if (t + 2 <= ke) att_issue(sb, s, t + 2, q0, bh, tid);
        CP_COMMIT();
    }

    // ---- normalize + store ----
    const float inv0 = 1.f / l_[0];
    const float inv1 = 1.f / l_[1];
    const size_t base0 = ((size_t)b * SS + row0) * EE + h * 64;
    const size_t base1 = base0 + (size_t)8 * EE;
#pragma unroll
    for (int dt = 0; dt < 8; dt++) {
        const int d = dt * 8 + colb;
        float2 w0 = make_float2(o[dt][0] * inv0, o[dt][1] * inv0);
        float2 w1 = make_float2(o[dt][2] * inv1, o[dt][3] * inv1);
        *(float2*)&out[base0 + d] = w0;
        *(float2*)&out[base1 + d] = w1;
    }
}

// ---------------------------------------------------------------------------
extern "C" void kernel_launch(void* const* d_in, const int* in_sizes, int n_in,
                              void* d_out, int out_size) {
    const float* hs  = (const float*)d_in[0];
    const int*   am  = (const int*)d_in[1];
    const float* q_w = (const float*)d_in[2];
    const float* q_b = (const float*)d_in[3];
    const float* k_w = (const float*)d_in[4];
    const float* k_b = (const float*)d_in[5];
    const float* v_w = (const float*)d_in[6];
    const float* v_b = (const float*)d_in[7];
    float* out = (float*)d_out;

    cudaFuncSetAttribute(qkv_hmma_gemm, cudaFuncAttributeMaxDynamicSharedMemorySize,
                         GEMM_SMEM);
    cudaFuncSetAttribute(attn_hmma, cudaFuncAttributeMaxDynamicSharedMemorySize,
                         ATT_SMEM);

    conv_x<<<(BB * SS * EE) / 1024, 256>>>(hs);
    conv_w<<<(3 * EE * EE) / 1024, 256>>>(q_w, k_w, v_w);

    dim3 g(NTOT / NT, (BB * SS) / MT);   // (24, 64)
    qkv_hmma_gemm<<<g, 256, GEMM_SMEM>>>(q_b, k_b, v_b);

    attn_hmma<<<BB * HH * (SS / 64), 128, ATT_SMEM>>>(am, out);
}

// round 9
// speedup vs baseline: 7.7673x; 1.0308x over previous
#include <cuda_runtime.h>
#include <cuda_fp16.h>
#include <cstdint>
#include <math.h>

#define BB 2
#define SS 4096
#define EE 1024
#define HH 16
#define DD 64
#define WW 256

#define NTOT 3072
#define NCHUNK 16

typedef unsigned long long u64;

// ---------------- scratch (__device__ globals, no allocs) -------------------
__device__ __align__(16) __half g_Qb[BB * HH * SS * DD];  // [B,H,S,D] fp16
__device__ __align__(16) __half g_Kb[BB * HH * SS * DD];  // [B,H,S,D] fp16
__device__ __align__(16) __half g_VT[BB * HH * DD * SS];  // [B,H,D,S] fp16
__device__ __align__(16) __half g_Xf[BB * SS * EE];       // fp16 hidden states
__device__ __align__(16) __half g_Wf[NTOT * EE];          // fp16 Q|K|V weights

// ---------------- PTX helpers ----------------------------------------------
__device__ __forceinline__ uint32_t smem_u32(const void* p) {
    uint32_t a;
    asm("{ .reg .u64 t; cvta.to.shared.u64 t, %1; cvt.u32.u64 %0, t; }" : "=r"(a) : "l"(p));
    return a;
}
#define SWZ(o) ((o) ^ (((o) >> 3) & 0x70))

__device__ __forceinline__ void cp16(uint32_t s, const void* g) {
    asm volatile("cp.async.cg.shared.global [%0], [%1], 16;" :: "r"(s), "l"(g));
}
#define CP_COMMIT() asm volatile("cp.async.commit_group;" ::: "memory")
#define CP_WAIT1()  asm volatile("cp.async.wait_group 1;" ::: "memory")
#define CP_WAIT2()  asm volatile("cp.async.wait_group 2;" ::: "memory")

__device__ __forceinline__ void ldsm4(uint32_t* r, uint32_t addr) {
    asm volatile("ldmatrix.sync.aligned.m8n8.x4.shared.b16 {%0,%1,%2,%3}, [%4];"
                 : "=r"(r[0]), "=r"(r[1]), "=r"(r[2]), "=r"(r[3]) : "r"(addr));
}
__device__ __forceinline__ void mma16816h(float* c, const uint32_t* a, uint32_t b0, uint32_t b1) {
    asm volatile("mma.sync.aligned.m16n8k16.row.col.f32.f16.f16.f32 "
                 "{%0,%1,%2,%3}, {%4,%5,%6,%7}, {%8,%9}, {%0,%1,%2,%3};"
                 : "+f"(c[0]), "+f"(c[1]), "+f"(c[2]), "+f"(c[3])
                 : "r"(a[0]), "r"(a[1]), "r"(a[2]), "r"(a[3]), "r"(b0), "r"(b1));
}
__device__ __forceinline__ uint32_t packh2(float lo, float hi) {
    uint32_t r;
    asm("cvt.rn.f16x2.f32 %0, %1, %2;" : "=r"(r) : "f"(hi), "f"(lo));
    return r;
}

// ---------------- fused fp32 -> fp16 convert --------------------------------
#define XELEM (BB * SS * EE)

__global__ void __launch_bounds__(256) conv_all(const float* __restrict__ X,
                                                const float* __restrict__ qw,
                                                const float* __restrict__ kw,
                                                const float* __restrict__ vw) {
    size_t i = ((size_t)blockIdx.x * 256 + threadIdx.x) * 4;
    if (i < XELEM) {
        float4 v = *(const float4*)(X + i);
        uint2 pk;
        pk.x = packh2(v.x, v.y);
        pk.y = packh2(v.z, v.w);
        *(uint2*)&g_Xf[i] = pk;
    } else {
        size_t j = i - XELEM;
        int proj = (int)(j >> 20);
        const float* W = (proj == 0) ? qw : (proj == 1) ? kw : vw;
        size_t loc = j & ((1u << 20) - 1);
        float4 v = *(const float4*)(W + loc);
        uint2 pk;
        pk.x = packh2(v.x, v.y);
        pk.y = packh2(v.z, v.w);
        *(uint2*)&g_Wf[j] = pk;
    }
}

// ---------------- HMMA QKV GEMM (fp16, 4 warps, 64x64 warp tile) ------------
#define GEMM_SMEM 98304

__device__ __forceinline__ void issue_loads(uint32_t sb, int stage, int chunk,
                                            int m0, int n0, int tid) {
    const int kc = chunk * 64;
    const uint32_t Ab = sb + stage * 32768;
    const uint32_t Bb = Ab + 16384;
#pragma unroll
    for (int i = 0; i < 8; i++) {
        int u = tid + i * 128;
        int r = u >> 3, p = u & 7;
        cp16(Ab + SWZ(r * 128 + p * 16), (const void*)(g_Xf + (size_t)(m0 + r) * EE + kc + p * 8));
    }
#pragma unroll
    for (int i = 0; i < 8; i++) {
        int u = tid + i * 128;
        int r = u >> 3, p = u & 7;
        cp16(Bb + SWZ(r * 128 + p * 16), (const void*)(g_Wf + (size_t)(n0 + r) * EE + kc + p * 8));
    }
}

__global__ void __launch_bounds__(128) qkv_hmma_gemm(const float* __restrict__ qb,
                                                     const float* __restrict__ kb,
                                                     const float* __restrict__ vb) {
    extern __shared__ char smraw[];
    const uint32_t sb = smem_u32(smraw);
    const int tid = threadIdx.x;
    const int wid = tid >> 5;
    const int lane = tid & 31;
    const int n0 = blockIdx.x * 128;
    const int m0 = blockIdx.y * 128;

    const int warpRow = (wid & 1) * 64;
    const int warpCol = (wid >> 1) * 64;
    const int lrow = lane & 15;
    const int lsel = (lane >> 4) * 16;

    float acc[4][8][4];
#pragma unroll
    for (int mi = 0; mi < 4; mi++)
#pragma unroll
        for (int ni = 0; ni < 8; ni++)
#pragma unroll
            for (int r = 0; r < 4; r++) acc[mi][ni][r] = 0.f;

    issue_loads(sb, 0, 0, m0, n0, tid); CP_COMMIT();
    issue_loads(sb, 1, 1, m0, n0, tid); CP_COMMIT();
    issue_loads(sb, 2, 2, m0, n0, tid); CP_COMMIT();

    int stage = 0;
    for (int c = 0; c < NCHUNK; c++) {
        CP_WAIT2();
        __syncthreads();
        const uint32_t Ab = sb + stage * 32768;
        const uint32_t Bb = Ab + 16384;
#pragma unroll
        for (int kk = 0; kk < 4; kk++) {
            uint32_t afr[4][4];
#pragma unroll
            for (int mi = 0; mi < 4; mi++) {
                uint32_t o = (warpRow + mi * 16 + lrow) * 128 + kk * 32 + lsel;
                ldsm4(afr[mi], Ab + SWZ(o));
            }
            uint32_t bfr[4][4];
#pragma unroll
            for (int bi = 0; bi < 4; bi++) {
                uint32_t o = (warpCol + bi * 16 + lrow) * 128 + kk * 32 + lsel;
                ldsm4(bfr[bi], Bb + SWZ(o));
            }
#pragma unroll
            for (int mi = 0; mi < 4; mi++)
#pragma unroll
                for (int ni = 0; ni < 8; ni++)
                    mma16816h(acc[mi][ni], afr[mi],
                              bfr[ni >> 1][ni & 1], bfr[ni >> 1][(ni & 1) + 2]);
        }
        __syncthreads();
        if (c + 3 < NCHUNK) issue_loads(sb, stage, c + 3, m0, n0, tid);
        CP_COMMIT();
        stage = (stage == 2) ? 0 : stage + 1;
    }
    __syncthreads();

    // -------- epilogue: stage C in smem, bias + fp16 + layout transform -----
    float* Cs = (float*)smraw;   // [128][132]
#pragma unroll
    for (int mi = 0; mi < 4; mi++)
#pragma unroll
        for (int ni = 0; ni < 8; ni++) {
            const int r = warpRow + mi * 16 + (lane >> 2);
            const int col = warpCol + ni * 8 + (lane & 3) * 2;
            Cs[r * 132 + col]       = acc[mi][ni][0];
            Cs[r * 132 + col + 1]   = acc[mi][ni][1];
            Cs[(r + 8) * 132 + col]     = acc[mi][ni][2];
            Cs[(r + 8) * 132 + col + 1] = acc[mi][ni][3];
        }
    __syncthreads();

    const int proj = n0 >> 10;
    const int nb1023 = n0 & 1023;
    const int h0 = nb1023 >> 6;
    const int b = m0 >> 12;
    const int s_base = m0 & (SS - 1);

    if (proj < 2) {
        __half* dst = (proj == 0) ? g_Qb : g_Kb;
        const float* bp = (proj == 0) ? qb : kb;
        const float scale = (proj == 0) ? 0.125f : 1.0f;
#pragma unroll
        for (int it = 0; it < 32; it++) {
            const int id = tid + it * 128;
            const int col = (id & 31) * 4;
            const int s = id >> 5;
            const int h = h0 + (col >> 6);
            const int d = col & 63;
            float v0 = (Cs[s * 132 + col]     + bp[nb1023 + col])     * scale;
            float v1 = (Cs[s * 132 + col + 1] + bp[nb1023 + col + 1]) * scale;
            float v2 = (Cs[s * 132 + col + 2] + bp[nb1023 + col + 2]) * scale;
            float v3 = (Cs[s * 132 + col + 3] + bp[nb1023 + col + 3]) * scale;
            uint2 pk;
            pk.x = packh2(v0, v1);
            pk.y = packh2(v2, v3);
            *(uint2*)&dst[((size_t)(b * HH + h) * SS + s_base + s) * DD + d] = pk;
        }
    } else {
#pragma unroll
        for (int it = 0; it < 32; it++) {
            const int id = tid + it * 128;
            const int col = id >> 5;
            const int s4 = (id & 31) * 4;
            const int h = h0 + (col >> 6);
            const int d = col & 63;
            const float bv = vb[nb1023 + col];
            float v0 = Cs[(s4 + 0) * 132 + col] + bv;
            float v1 = Cs[(s4 + 1) * 132 + col] + bv;
            float v2 = Cs[(s4 + 2) * 132 + col] + bv;
            float v3 = Cs[(s4 + 3) * 132 + col] + bv;
            uint2 pk;
            pk.x = packh2(v0, v1);
            pk.y = packh2(v2, v3);
            *(uint2*)&g_VT[((size_t)(b * HH + h) * DD + d) * SS + s_base + s4] = pk;
        }
    }
}

// ---------------- HMMA banded flash attention (fp16) ------------------------
// SMEM: Qs 8KB @0, stage0 K 8KB @8192, V 8KB @16384, stage1 @24576/32768,
// fms 576 floats @40960. Total 43264 B.
#define ATT_SMEM 43264

__device__ __forceinline__ void att_issue(uint32_t sb, int stage, int t,
                                          int q0, int bh, int tid) {
    const int j0 = q0 - WW + t * 64;   // always in [0, SS-64] given ks/ke
    const uint32_t Kb = sb + 8192 + stage * 16384;
    const uint32_t Vb = Kb + 8192;
    const __half* Kg = g_Kb + (size_t)bh * SS * DD + (size_t)j0 * DD;
    const __half* Vg = g_VT + (size_t)bh * DD * SS + j0;
#pragma unroll
    for (int i = 0; i < 4; i++) {
        const int u = tid + i * 128;
        const int r = u >> 3, p = u & 7;
        cp16(Kb + SWZ(r * 128 + p * 16), (const void*)(Kg + (size_t)r * DD + p * 8));
        cp16(Vb + SWZ(r * 128 + p * 16), (const void*)(Vg + (size_t)r * SS + p * 8));
    }
}

__global__ void __launch_bounds__(128, 4) attn_hmma(const int* __restrict__ amask,
                                                    float* __restrict__ out) {
    extern __shared__ char smraw[];
    const uint32_t sb = smem_u32(smraw);
    float* fms = (float*)(smraw + 40960);

    const int tid = threadIdx.x;
    const int wid = tid >> 5;
    const int lane = tid & 31;
    const int qt = blockIdx.x & 63;
    const int h = (blockIdx.x >> 6) & 15;
    const int b = blockIdx.x >> 10;
    const int q0 = qt * 64;
    const int bh = b * HH + h;

    // Load Q tile (fp16, swizzled)
    {
        const __half* Qg = g_Qb + (size_t)(bh * SS + q0) * DD;
#pragma unroll
        for (int i = 0; i < 4; i++) {
            const int u = tid + i * 128;
            const int r = u >> 3, p = u & 7;
            uint4 v = *(const uint4*)(Qg + r * DD + p * 8);
            *(uint4*)(smraw + SWZ(r * 128 + p * 16)) = v;
        }
    }
    // fms for whole 576-key span + detect if any mask active
    int localmask = 0;
    for (int c = tid; c < 576; c += 128) {
        const int j = q0 - WW + c;
        const int mv = (j >= 0 && j < SS) ? amask[b * SS + j] : 0;
        fms[c] = (mv != 0) ? -10000.f : 0.f;
        localmask |= mv;
    }

    const int ks = (qt < 4) ? (4 - qt) : 0;
    const int ke = (qt > 59) ? (67 - qt) : 8;

    att_issue(sb, 0, ks, q0, bh, tid); CP_COMMIT();
    if (ks + 1 <= ke) att_issue(sb, 1, ks + 1, q0, bh, tid);
    CP_COMMIT();
    const int anymask = __syncthreads_or(localmask);

    // Q fragments (held for whole block)
    const int lrow = lane & 15;
    const int lsel = (lane >> 4) * 16;
    uint32_t qf[4][4];
#pragma unroll
    for (int kk = 0; kk < 4; kk++)
        ldsm4(qf[kk], sb + SWZ((wid * 16 + lrow) * 128 + kk * 32 + lsel));

    const int row0 = q0 + wid * 16 + (lane >> 2);
    const int row1 = row0 + 8;
    const int colb = (lane & 3) * 2;

    float m_[2] = {-1e30f, -1e30f};
    float l_[2] = {0.f, 0.f};
    float o[8][4];
#pragma unroll
    for (int dt = 0; dt < 8; dt++)
#pragma unroll
        for (int r = 0; r < 4; r++) o[dt][r] = 0.f;

    for (int t = ks; t <= ke; t++) {
        const int s = (t - ks) & 1;
        CP_WAIT1();
        __syncthreads();
        const int j0 = q0 - WW + t * 64;
        const uint32_t Kb = sb + 8192 + s * 16384;
        const uint32_t Vb = Kb + 8192;

        // ---- scores S = Q K^T ----
        float sf[8][4];
#pragma unroll
        for (int nt = 0; nt < 8; nt++)
#pragma unroll
            for (int r = 0; r < 4; r++) sf[nt][r] = 0.f;

#pragma unroll
        for (int kk = 0; kk < 4; kk++) {
            uint32_t bfr[4][4];
#pragma unroll
            for (int nn = 0; nn < 4; nn++)
                ldsm4(bfr[nn], Kb + SWZ((nn * 16 + lrow) * 128 + kk * 32 + lsel));
#pragma unroll
            for (int nt = 0; nt < 8; nt++)
                mma16816h(sf[nt], qf[kk],
                          bfr[nt >> 1][nt & 1], bfr[nt >> 1][(nt & 1) + 2]);
        }

        // ---- mask + online softmax ----
        // All loaded tiles lie fully within [0,SS). Band |j-i|<=W only fails
        // in tiles t==0 / t==8. fms adds only needed when any mask active.
        float rm0 = -INFINITY, rm1 = -INFINITY;
        if (anymask) {
            if (t == 0 || t == 8) {
#pragma unroll
                for (int nt = 0; nt < 8; nt++) {
#pragma unroll
                    for (int e = 0; e < 2; e++) {
                        const int kl = nt * 8 + colb + e;
                        const int j = j0 + kl;
                        const float fmv = fms[t * 64 + kl];
                        const bool v0 = (j - row0 <= WW) && (row0 - j <= WW);
                        const bool v1 = (j - row1 <= WW) && (row1 - j <= WW);
                        sf[nt][e]     = v0 ? sf[nt][e] + fmv     : -INFINITY;
                        sf[nt][2 + e] = v1 ? sf[nt][2 + e] + fmv : -INFINITY;
                        rm0 = fmaxf(rm0, sf[nt][e]);
                        rm1 = fmaxf(rm1, sf[nt][2 + e]);
                    }
                }
            } else {
#pragma unroll
                for (int nt = 0; nt < 8; nt++) {
                    const float fmv0 = fms[t * 64 + nt * 8 + colb];
                    const float fmv1 = fms[t * 64 + nt * 8 + colb + 1];
                    sf[nt][0] += fmv0; sf[nt][1] += fmv1;
                    sf[nt][2] += fmv0; sf[nt][3] += fmv1;
                    rm0 = fmaxf(rm0, fmaxf(sf[nt][0], sf[nt][1]));
                    rm1 = fmaxf(rm1, fmaxf(sf[nt][2], sf[nt][3]));
                }
            }
        } else {
            if (t == 0 || t == 8) {
#pragma unroll
                for (int nt = 0; nt < 8; nt++) {
#pragma unroll
                    for (int e = 0; e < 2; e++) {
                        const int kl = nt * 8 + colb + e;
                        const int j = j0 + kl;
                        const bool v0 = (j - row0 <= WW) && (row0 - j <= WW);
                        const bool v1 = (j - row1 <= WW) && (row1 - j <= WW);
                        sf[nt][e]     = v0 ? sf[nt][e]     : -INFINITY;
                        sf[nt][2 + e] = v1 ? sf[nt][2 + e] : -INFINITY;
                        rm0 = fmaxf(rm0, sf[nt][e]);
                        rm1 = fmaxf(rm1, sf[nt][2 + e]);
                    }
                }
            } else {
#pragma unroll
                for (int nt = 0; nt < 8; nt++) {
                    rm0 = fmaxf(rm0, fmaxf(sf[nt][0], sf[nt][1]));
                    rm1 = fmaxf(rm1, fmaxf(sf[nt][2], sf[nt][3]));
                }
            }
        }
        rm0 = fmaxf(rm0, __shfl_xor_sync(0xffffffffu, rm0, 1));
        rm0 = fmaxf(rm0, __shfl_xor_sync(0xffffffffu, rm0, 2));
        rm1 = fmaxf(rm1, __shfl_xor_sync(0xffffffffu, rm1, 1));
        rm1 = fmaxf(rm1, __shfl_xor_sync(0xffffffffu, rm1, 2));

        const float mn0 = fmaxf(m_[0], rm0);
        const float mn1 = fmaxf(m_[1], rm1);
        const float fs0 = __expf(m_[0] - mn0);
        const float fs1 = __expf(m_[1] - mn1);
        m_[0] = mn0; m_[1] = mn1;

        float rs0 = 0.f, rs1 = 0.f;
#pragma unroll
        for (int nt = 0; nt < 8; nt++) {
            sf[nt][0] = __expf(sf[nt][0] - mn0);
            sf[nt][1] = __expf(sf[nt][1] - mn0);
            sf[nt][2] = __expf(sf[nt][2] - mn1);
            sf[nt][3] = __expf(sf[nt][3] - mn1);
            rs0 += sf[nt][0] + sf[nt][1];
            rs1 += sf[nt][2] + sf[nt][3];
        }
        rs0 += __shfl_xor_sync(0xffffffffu, rs0, 1);
        rs0 += __shfl_xor_sync(0xffffffffu, rs0, 2);
        rs1 += __shfl_xor_sync(0xffffffffu, rs1, 1);
        rs1 += __shfl_xor_sync(0xffffffffu, rs1, 2);
        l_[0] = l_[0] * fs0 + rs0;
        l_[1] = l_[1] * fs1 + rs1;

#pragma unroll
        for (int dt = 0; dt < 8; dt++) {
            o[dt][0] *= fs0; o[dt][1] *= fs0;
            o[dt][2] *= fs1; o[dt][3] *= fs1;
        }

        // ---- P fragments (accumulator -> A-operand identity, fp16) ----
        uint32_t pf[4][4];
#pragma unroll
        for (int kc = 0; kc < 4; kc++) {
            pf[kc][0] = packh2(sf[2 * kc][0],     sf[2 * kc][1]);
            pf[kc][1] = packh2(sf[2 * kc][2],     sf[2 * kc][3]);
            pf[kc][2] = packh2(sf[2 * kc + 1][0], sf[2 * kc + 1][1]);
            pf[kc][3] = packh2(sf[2 * kc + 1][2], sf[2 * kc + 1][3]);
        }

        // ---- O += P V ----
#pragma unroll
        for (int kc = 0; kc < 4; kc++) {
            uint32_t vfr[4][4];
#pragma unroll
            for (int nn = 0; nn < 4; nn++)
                ldsm4(vfr[nn], Vb + SWZ((nn * 16 + lrow) * 128 + kc * 32 + lsel));
#pragma unroll
            for (int dt = 0; dt < 8; dt++)
                mma16816h(o[dt], pf[kc],
                          vfr[dt >> 1][dt & 1], vfr[dt >> 1][(dt & 1) + 2]);
        }

        __syncthreads();
        if (t + 2 <= ke) att_issue(sb, s, t + 2, q0, bh, tid);
        CP_COMMIT();
    }

    // ---- normalize + store ----
    const float inv0 = 1.f / l_[0];
    const float inv1 = 1.f / l_[1];
    const size_t base0 = ((size_t)b * SS + row0) * EE + h * 64;
    const size_t base1 = base0 + (size_t)8 * EE;
#pragma unroll
    for (int dt = 0; dt < 8; dt++) {
        const int d = dt * 8 + colb;
        float2 w0 = make_float2(o[dt][0] * inv0, o[dt][1] * inv0);
        float2 w1 = make_float2(o[dt][2] * inv1, o[dt][3] * inv1);
        *(float2*)&out[base0 + d] = w0;
        *(float2*)&out[base1 + d] = w1;
    }
}

// ---------------------------------------------------------------------------
extern "C" void kernel_launch(void* const* d_in, const int* in_sizes, int n_in,
                              void* d_out, int out_size) {
    const float* hs  = (const float*)d_in[0];
    const int*   am  = (const int*)d_in[1];
    const float* q_w = (const float*)d_in[2];
    const float* q_b = (const float*)d_in[3];
    const float* k_w = (const float*)d_in[4];
    const float* k_b = (const float*)d_in[5];
    const float* v_w = (const float*)d_in[6];
    const float* v_b = (const float*)d_in[7];
    float* out = (float*)d_out;

    cudaFuncSetAttribute(qkv_hmma_gemm, cudaFuncAttributeMaxDynamicSharedMemorySize,
                         GEMM_SMEM);
    cudaFuncSetAttribute(attn_hmma, cudaFuncAttributeMaxDynamicSharedMemorySize,
                         ATT_SMEM);

    conv_all<<<(XELEM + 3 * EE * EE) / 1024, 256>>>(hs, q_w, k_w, v_w);

    dim3 g(NTOT / 128, (BB * SS) / 128);   // (24, 64)
    qkv_hmma_gemm<<<g, 128, GEMM_SMEM>>>(q_b, k_b, v_b);

    attn_hmma<<<BB * HH * (SS / 64), 128, ATT_SMEM>>>(am, out);
}